// round 14
// baseline (speedup 1.0000x reference)
#include <cuda_runtime.h>
#include <cuda_bf16.h>
#include <cuda_fp16.h>
#include <math.h>
#include <stdint.h>

// Problem constants
#define SEQ   2048
#define HID   2048
#define NH    16
#define HD    128
#define BATCH 2
#define MROWS (BATCH * SEQ)     // 4096
#define QKVN  (3 * HID)         // 6144
#define KA    2048              // fp16 row length (single plane)

// ---------------------------------------------------------------------------
// Scratch (device globals — no runtime allocation allowed)
// ---------------------------------------------------------------------------
__device__ __align__(16) float g_cos[SEQ * 64];
__device__ __align__(16) float g_sin[SEQ * 64];
__device__ __align__(16) __half g_xh [(size_t)MROWS * KA];     // x, fp16
__device__ __align__(16) __half g_wqp[(size_t)QKVN  * KA];     // Wqkv fp16
__device__ __align__(16) __half g_wop[(size_t)HID   * KA];     // Wout fp16
__device__ __align__(16) __half g_cxh[(size_t)MROWS * KA];     // ctx, fp16
// attention operands (fp16, single plane each, per-(b,h) planar)
__device__ __align__(16) __half g_qp[(size_t)BATCH * NH * SEQ * HD];
__device__ __align__(16) __half g_kp[(size_t)BATCH * NH * SEQ * HD];
__device__ __align__(16) __half g_vp[(size_t)BATCH * NH * SEQ * HD];

// ---------------------------------------------------------------------------
// PTX helpers (arch-agnostic: cp.async / ldmatrix / mma.sync only)
// ---------------------------------------------------------------------------
__device__ __forceinline__ uint32_t s2u(const void* p) {
    uint32_t a;
    asm("{ .reg .u64 t; cvta.to.shared.u64 t, %1; cvt.u32.u64 %0, t; }"
        : "=r"(a) : "l"(p));
    return a;
}

#define CP_ASYNC16(saddr, gptr) \
    asm volatile("cp.async.cg.shared.global [%0], [%1], 16;" \
                 :: "r"(saddr), "l"(gptr))
#define CP_COMMIT()  asm volatile("cp.async.commit_group;" ::: "memory")
#define CP_WAIT1()   asm volatile("cp.async.wait_group 1;" ::: "memory")
#define CP_WAIT2()   asm volatile("cp.async.wait_group 2;" ::: "memory")

#define LDSM4(r, addr)                                                        \
    asm volatile("ldmatrix.sync.aligned.m8n8.x4.shared.b16 {%0,%1,%2,%3}, [%4];" \
        : "=r"((r)[0]), "=r"((r)[1]), "=r"((r)[2]), "=r"((r)[3]) : "r"(addr))
#define LDSM4T(r, addr)                                                       \
    asm volatile("ldmatrix.sync.aligned.m8n8.x4.trans.shared.b16 {%0,%1,%2,%3}, [%4];" \
        : "=r"((r)[0]), "=r"((r)[1]), "=r"((r)[2]), "=r"((r)[3]) : "r"(addr))

// fp16 MMA
#define MMA16816H(d, a, b0, b1)                                               \
    asm volatile("mma.sync.aligned.m16n8k16.row.col.f32.f16.f16.f32 "         \
        "{%0,%1,%2,%3},{%4,%5,%6,%7},{%8,%9},{%0,%1,%2,%3};"                  \
        : "+f"((d)[0]), "+f"((d)[1]), "+f"((d)[2]), "+f"((d)[3])              \
        : "r"((a)[0]), "r"((a)[1]), "r"((a)[2]), "r"((a)[3]),                 \
          "r"(b0), "r"(b1))

__device__ __forceinline__ float ex2f(float x) {
    float y;
    asm("ex2.approx.ftz.f32 %0, %1;" : "=f"(y) : "f"(x));
    return y;
}
__device__ __forceinline__ uint32_t h2u(__half2 h) {
    return *(uint32_t*)&h;
}
__device__ __forceinline__ uint32_t packh(float lo, float hi) {
    __half2 h = __float22half2_rn(make_float2(lo, hi));
    return h2u(h);
}

// ---------------------------------------------------------------------------
// RoPE table (reference-matching numerics)
// ---------------------------------------------------------------------------
__global__ void rope_table_kernel() {
    int idx = blockIdx.x * blockDim.x + threadIdx.x;
    if (idx >= SEQ * 64) return;
    int s = idx >> 6;
    int j = idx & 63;
    double inv = exp(-((double)j / 64.0) * log(10000.0));
    float  invf = (float)inv;
    float  ang  = (float)s * invf;
    g_cos[idx] = (float)cos((double)ang);
    g_sin[idx] = (float)sin((double)ang);
}

// ---------------------------------------------------------------------------
// fp32 -> fp16 single-plane pack (8 elems/thread) — x and weights
// ---------------------------------------------------------------------------
__global__ void pack_x_kernel(const float* __restrict__ X,
                              __half* __restrict__ P, int n) {
    int i = (blockIdx.x * 256 + threadIdx.x) * 8;
    if (i >= n) return;
    float4 a = *(const float4*)(X + i);
    float4 b = *(const float4*)(X + i + 4);
    *(uint4*)(P + i) = make_uint4(
        packh(a.x, a.y), packh(a.z, a.w), packh(b.x, b.y), packh(b.z, b.w));
}

// ---------------------------------------------------------------------------
// Shared GEMM config (both GEMM kernels)
// ---------------------------------------------------------------------------
#define AST         72
#define STG_MAT     (128 * AST * 2)
#define STG_BYTES   (2 * STG_MAT)
#define GEMM_STAGES 3
#define GEMM_SMEM   (GEMM_STAGES * STG_BYTES)   // 110592
#define GNITER      32

__device__ __forceinline__ void g_load_stage(
    uint32_t sA, const __half* Ab, const __half* Bb, int tid)
{
#pragma unroll
    for (int t = 0; t < 8; t++) {
        int c = tid + t * 128;
        int r = c >> 3, co = (c & 7) << 3;
        CP_ASYNC16(sA + (r * AST + co) * 2, Ab + (size_t)r * KA + co);
        CP_ASYNC16(sA + STG_MAT + (r * AST + co) * 2, Bb + (size_t)r * KA + co);
    }
}

// Mainloop shared by both GEMMs: accumulates the 128x128 tile into acc.
__device__ __forceinline__ void gemm_mainloop(
    uint32_t smb, const __half* A, const __half* B,
    int m0, int n0, int tid, int lane, int wm, int wn,
    float acc[4][8][4])
{
    uint32_t a_off[4][4], b_off[4][4];
#pragma unroll
    for (int ks = 0; ks < 4; ks++) {
#pragma unroll
        for (int mt = 0; mt < 4; mt++)
            a_off[ks][mt] = ((wm + mt * 16 + (lane & 15)) * AST +
                             ks * 16 + (lane >> 4) * 8) * 2;
#pragma unroll
        for (int np = 0; np < 4; np++)
            b_off[ks][np] = STG_MAT +
                ((wn + np * 16 + ((lane >> 4) & 1) * 8 + (lane & 7)) * AST +
                 ks * 16 + ((lane >> 3) & 1) * 8) * 2;
    }

#pragma unroll
    for (int p = 0; p < GEMM_STAGES - 1; p++) {
        g_load_stage(smb + p * STG_BYTES,
                     A + (size_t)m0 * KA + (p << 6),
                     B + (size_t)n0 * KA + (p << 6), tid);
        CP_COMMIT();
    }
    CP_WAIT1();
    __syncthreads();

    uint32_t af[2][4][4], bf[2][4];
#pragma unroll
    for (int mt = 0; mt < 4; mt++) LDSM4(af[0][mt], smb + a_off[0][mt]);
    LDSM4(bf[0], smb + b_off[0][0]);

    for (int it = 0; it < GNITER; ++it) {
        uint32_t sbase = smb + (it % GEMM_STAGES) * STG_BYTES;

        int nx = it + GEMM_STAGES - 1;
        if (nx < GNITER) {
            g_load_stage(smb + (nx % GEMM_STAGES) * STG_BYTES,
                         A + (size_t)m0 * KA + (nx << 6),
                         B + (size_t)n0 * KA + (nx << 6), tid);
        }
        CP_COMMIT();

#pragma unroll
        for (int ks = 0; ks < 4; ks++) {
            int cur = ks & 1, nxt = cur ^ 1;
            uint32_t bb[2][4];
#pragma unroll
            for (int e = 0; e < 4; e++) bb[0][e] = bf[cur][e];
#pragma unroll
            for (int np = 0; np < 4; np++) {
                if (np < 3) LDSM4(bb[(np + 1) & 1], sbase + b_off[ks][np + 1]);
#pragma unroll
                for (int mt = 0; mt < 4; mt++) {
                    MMA16816H(acc[mt][2 * np],     af[cur][mt], bb[np & 1][0], bb[np & 1][1]);
                    MMA16816H(acc[mt][2 * np + 1], af[cur][mt], bb[np & 1][2], bb[np & 1][3]);
                }
            }
            if (ks < 3) {
#pragma unroll
                for (int mt = 0; mt < 4; mt++)
                    LDSM4(af[nxt][mt], sbase + a_off[ks + 1][mt]);
                LDSM4(bf[nxt], sbase + b_off[ks + 1][0]);
            }
        }

        CP_WAIT1();
        __syncthreads();
        uint32_t nbase = smb + ((it + 1) % GEMM_STAGES) * STG_BYTES;
#pragma unroll
        for (int mt = 0; mt < 4; mt++) LDSM4(af[0][mt], nbase + a_off[0][mt]);
        LDSM4(bf[0], nbase + b_off[0][0]);
    }
}

// ---------------------------------------------------------------------------
// Out-projection GEMM: fp32 epilogue to C (unchanged behavior)
// ---------------------------------------------------------------------------
__global__ void __launch_bounds__(128, 2) tc_gemm_kernel(
    const __half* __restrict__ A, const __half* __restrict__ B,
    float* __restrict__ C, int ldc)
{
    extern __shared__ char smg[];
    uint32_t smb = s2u(smg);
    int tid  = threadIdx.x;
    int lane = tid & 31, wid = tid >> 5;
    int wm = (wid & 1) * 64, wn = (wid >> 1) * 64;
    int m0 = blockIdx.y * 128, n0 = blockIdx.x * 128;

    float acc[4][8][4];
#pragma unroll
    for (int i = 0; i < 4; i++)
#pragma unroll
        for (int j = 0; j < 8; j++)
#pragma unroll
            for (int k = 0; k < 4; k++) acc[i][j][k] = 0.f;

    gemm_mainloop(smb, A, B, m0, n0, tid, lane, wm, wn, acc);

    float* Cb = C + (size_t)(m0 + wm) * ldc + n0 + wn;
    int rq = lane >> 2, cq = (lane & 3) * 2;
#pragma unroll
    for (int mt = 0; mt < 4; mt++)
#pragma unroll
        for (int nt = 0; nt < 8; nt++) {
            *(float2*)(Cb + (size_t)(mt * 16 + rq) * ldc + nt * 8 + cq) =
                make_float2(acc[mt][nt][0], acc[mt][nt][1]);
            *(float2*)(Cb + (size_t)(mt * 16 + rq + 8) * ldc + nt * 8 + cq) =
                make_float2(acc[mt][nt][2], acc[mt][nt][3]);
        }
}

// ---------------------------------------------------------------------------
// QKV GEMM with FUSED RoPE + fp16 pack epilogue.
// Each 128-col tile = one head of q, k, or v (region = n0>>11).
// acc staged through smem (fp32, stride 132), then RoPE'd/converted and
// written directly to the planar fp16 attention operands.
// ---------------------------------------------------------------------------
#define EP_STR 132

__global__ void __launch_bounds__(128, 2) tc_gemm_qkv_kernel(
    const __half* __restrict__ A, const __half* __restrict__ B)
{
    extern __shared__ char smg[];
    uint32_t smb = s2u(smg);
    int tid  = threadIdx.x;
    int lane = tid & 31, wid = tid >> 5;
    int wm = (wid & 1) * 64, wn = (wid >> 1) * 64;
    int m0 = blockIdx.y * 128, n0 = blockIdx.x * 128;

    float acc[4][8][4];
#pragma unroll
    for (int i = 0; i < 4; i++)
#pragma unroll
        for (int j = 0; j < 8; j++)
#pragma unroll
            for (int k = 0; k < 4; k++) acc[i][j][k] = 0.f;

    gemm_mainloop(smb, A, B, m0, n0, tid, lane, wm, wn, acc);

    // ---- stage acc tile into smem (fp32) ----
    __syncthreads();                 // all warps past mainloop smem reads
    float* st = (float*)smg;
    int rq = lane >> 2, cq2 = (lane & 3) * 2;
#pragma unroll
    for (int mt = 0; mt < 4; mt++)
#pragma unroll
        for (int nt = 0; nt < 8; nt++) {
            int c = wn + nt * 8 + cq2;
            *(float2*)&st[(wm + mt * 16 + rq) * EP_STR + c] =
                make_float2(acc[mt][nt][0], acc[mt][nt][1]);
            *(float2*)&st[(wm + mt * 16 + rq + 8) * EP_STR + c] =
                make_float2(acc[mt][nt][2], acc[mt][nt][3]);
        }
    __syncthreads();

    int region = n0 >> 11;           // 0:q 1:k 2:v
    int head   = (n0 & 2047) >> 7;

    if (region < 2) {
        __half* dst = (region == 0) ? g_qp : g_kp;
        // 128 rows x 16 j-groups (j = jg..jg+3, pairs with j+64)
        for (int t = tid; t < 2048; t += 128) {
            int r  = t >> 4;
            int jg = (t & 15) << 2;
            int gr = m0 + r;
            int s  = gr & (SEQ - 1);
            int bh = (gr >> 11) * NH + head;
            float4 S1 = *(float4*)&st[r * EP_STR + jg];
            float4 S2 = *(float4*)&st[r * EP_STR + jg + 64];
            float4 c4 = *(const float4*)&g_cos[(s << 6) + jg];
            float4 s4 = *(const float4*)&g_sin[(s << 6) + jg];
            float a0 = S1.x * c4.x - S2.x * s4.x;
            float a1 = S1.y * c4.y - S2.y * s4.y;
            float a2 = S1.z * c4.z - S2.z * s4.z;
            float a3 = S1.w * c4.w - S2.w * s4.w;
            float b0 = S2.x * c4.x + S1.x * s4.x;
            float b1 = S2.y * c4.y + S1.y * s4.y;
            float b2 = S2.z * c4.z + S1.z * s4.z;
            float b3 = S2.w * c4.w + S1.w * s4.w;
            size_t base = ((size_t)bh * SEQ + s) * HD;
            *(uint2*)(dst + base + jg) =
                make_uint2(packh(a0, a1), packh(a2, a3));
            *(uint2*)(dst + base + jg + 64) =
                make_uint2(packh(b0, b1), packh(b2, b3));
        }
    } else {
        // v: straight fp32 -> fp16, 8 elems per work item
        for (int t = tid; t < 2048; t += 128) {
            int r  = t >> 4;
            int jg = (t & 15) << 3;
            int gr = m0 + r;
            int s  = gr & (SEQ - 1);
            int bh = (gr >> 11) * NH + head;
            float4 a = *(float4*)&st[r * EP_STR + jg];
            float4 b = *(float4*)&st[r * EP_STR + jg + 4];
            size_t base = ((size_t)bh * SEQ + s) * HD;
            *(uint4*)(g_vp + base + jg) = make_uint4(
                packh(a.x, a.y), packh(a.z, a.w),
                packh(b.x, b.y), packh(b.z, b.w));
        }
    }
}

// ---------------------------------------------------------------------------
// Tensor-core flash attention (fp16 1-pass, causal, online softmax, LPT grid,
// 3-stage KV ring, 1 sync/K-tile, fused fp16 ctx epilogue).
// Unchanged from round 13 (passing).
// ---------------------------------------------------------------------------
#define AKST     136
#define AROWB    (AKST * 2)                 // 272 B
#define QPLANE   (128 * AROWB)              // 34816
#define KVPLANE  (64 * AROWB)               // 17408
#define STAGE_B  (2 * KVPLANE)              // 34816 (K + V)
#define KVSTAGES 3
#define ATTN_SMEM (KVSTAGES * STAGE_B)      // 104448

__device__ __forceinline__ void load_kv_stage(
    uint32_t dst, const __half* Kp, const __half* Vp, int k0, int tid)
{
#pragma unroll
    for (int t = 0; t < 8; t++) {
        int c = tid + t * 256;
        int plane = c >> 10;                // 0:K 1:V
        int r = (c >> 4) & 63;
        int co = c & 15;
        const __half* src = (plane == 0)
            ? Kp + ((size_t)k0 + r) * HD + co * 8
            : Vp + ((size_t)k0 + r) * HD + co * 8;
        CP_ASYNC16(dst + plane * KVPLANE + r * AROWB + co * 16, src);
    }
}

__global__ void __launch_bounds__(256) attn_mma_kernel() {
    extern __shared__ char sma[];
    uint32_t smb = s2u(sma);
    int tid = threadIdx.x, lane = tid & 31, w = tid >> 5;
    int qt = 15 - ((int)blockIdx.x >> 5);   // LPT: heaviest first
    int bh = (int)blockIdx.x & 31;
    int q0 = qt * 128;
    int nkt = 2 * qt + 2;

    const __half* Qp = g_qp + (size_t)bh * SEQ * HD;
    const __half* Kp = g_kp + (size_t)bh * SEQ * HD;
    const __half* Vp = g_vp + (size_t)bh * SEQ * HD;

    uint32_t sQstage = smb + 2 * STAGE_B;
#pragma unroll
    for (int t = 0; t < 8; t++) {
        int c = tid + t * 256;
        int r = c >> 4, co = c & 15;
        CP_ASYNC16(sQstage + r * AROWB + co * 16,
                   Qp + ((size_t)q0 + r) * HD + co * 8);
    }
    CP_COMMIT();
    load_kv_stage(smb, Kp, Vp, 0, tid);
    CP_COMMIT();
    load_kv_stage(smb + STAGE_B, Kp, Vp, 64, tid);
    CP_COMMIT();

    int rq = lane >> 2, cq = lane & 3;
    uint32_t qoff = (uint32_t)(16 * w + (lane & 15)) * AROWB + ((lane >> 4) & 1) * 16;
    uint32_t koff = (uint32_t)(((lane >> 4) & 1) * 8 + (lane & 7)) * AROWB +
                    ((lane >> 3) & 1) * 16;
    uint32_t voff = KVPLANE +
                    (uint32_t)(((lane >> 3) & 1) * 8 + (lane & 7)) * AROWB +
                    ((lane >> 4) & 1) * 16;

    CP_WAIT2();
    __syncthreads();
    uint32_t qfh[8][4];
#pragma unroll
    for (int kc = 0; kc < 8; kc++)
        LDSM4(qfh[kc], sQstage + qoff + kc * 32);

    float out[16][4];
#pragma unroll
    for (int n = 0; n < 16; n++)
#pragma unroll
        for (int e = 0; e < 4; e++) out[n][e] = 0.f;
    float m0 = -1e30f, m1 = -1e30f, l0 = 0.f, l1 = 0.f;

    const float SCALE2 = 0.08838834764831845f * 1.44269504088896341f;

    for (int kt = 0; kt < nkt; kt++) {
        CP_WAIT1();
        __syncthreads();
        if (kt + 2 < nkt)
            load_kv_stage(smb + ((kt + 2) % KVSTAGES) * STAGE_B, Kp, Vp,
                          (kt + 2) * 64, tid);
        CP_COMMIT();

        uint32_t sS = smb + (kt % KVSTAGES) * STAGE_B;

        float sc[8][4];
#pragma unroll
        for (int j = 0; j < 8; j++)
#pragma unroll
            for (int e = 0; e < 4; e++) sc[j][e] = 0.f;

        {
            uint32_t bkh[2][4];
            LDSM4(bkh[0], sS + koff);
#pragma unroll
            for (int t = 0; t < 32; t++) {
                int kc = t >> 2, jj = t & 3;
                int cur = t & 1;
                if (t < 31) {
                    int tn = t + 1;
                    uint32_t on = koff + (uint32_t)(tn & 3) * (16 * AROWB) +
                                  (tn >> 2) * 32;
                    LDSM4(bkh[cur ^ 1], sS + on);
                }
                MMA16816H(sc[2 * jj],     qfh[kc], bkh[cur][0], bkh[cur][1]);
                MMA16816H(sc[2 * jj + 1], qfh[kc], bkh[cur][2], bkh[cur][3]);
            }
        }

        int k0 = kt * 64;
#pragma unroll
        for (int j = 0; j < 8; j++)
#pragma unroll
            for (int e = 0; e < 4; e++) sc[j][e] *= SCALE2;
        if (k0 + 64 > q0) {
            int rg0 = q0 + 16 * w + rq, rg1 = rg0 + 8;
#pragma unroll
            for (int j = 0; j < 8; j++) {
                int cg = k0 + 8 * j + 2 * cq;
                if (cg     > rg0) sc[j][0] = -1e30f;
                if (cg + 1 > rg0) sc[j][1] = -1e30f;
                if (cg     > rg1) sc[j][2] = -1e30f;
                if (cg + 1 > rg1) sc[j][3] = -1e30f;
            }
        }

        float t0 = -1e30f, t1 = -1e30f;
#pragma unroll
        for (int j = 0; j < 8; j++) {
            t0 = fmaxf(t0, fmaxf(sc[j][0], sc[j][1]));
            t1 = fmaxf(t1, fmaxf(sc[j][2], sc[j][3]));
        }
        t0 = fmaxf(t0, __shfl_xor_sync(0xffffffffu, t0, 1));
        t0 = fmaxf(t0, __shfl_xor_sync(0xffffffffu, t0, 2));
        t1 = fmaxf(t1, __shfl_xor_sync(0xffffffffu, t1, 1));
        t1 = fmaxf(t1, __shfl_xor_sync(0xffffffffu, t1, 2));
        float mn0 = fmaxf(m0, t0), mn1 = fmaxf(m1, t1);
        float al0 = ex2f(m0 - mn0), al1 = ex2f(m1 - mn1);
        m0 = mn0; m1 = mn1;
        l0 *= al0; l1 *= al1;
#pragma unroll
        for (int n = 0; n < 16; n++) {
            out[n][0] *= al0; out[n][1] *= al0;
            out[n][2] *= al1; out[n][3] *= al1;
        }

#pragma unroll
        for (int kc = 0; kc < 4; kc++) {
            int j0 = 2 * kc, j1 = 2 * kc + 1;
            float p00 = ex2f(sc[j0][0] - m0), p01 = ex2f(sc[j0][1] - m0);
            float p02 = ex2f(sc[j0][2] - m1), p03 = ex2f(sc[j0][3] - m1);
            float p10 = ex2f(sc[j1][0] - m0), p11 = ex2f(sc[j1][1] - m0);
            float p12 = ex2f(sc[j1][2] - m1), p13 = ex2f(sc[j1][3] - m1);
            l0 += p00 + p01 + p10 + p11;
            l1 += p02 + p03 + p12 + p13;

            uint32_t ah[4];
            ah[0] = packh(p00, p01);
            ah[1] = packh(p02, p03);
            ah[2] = packh(p10, p11);
            ah[3] = packh(p12, p13);

            uint32_t bvh[2][4];
            uint32_t o0 = voff + (uint32_t)kc * (16 * AROWB);
            LDSM4T(bvh[0], sS + o0);
#pragma unroll
            for (int jp = 0; jp < 8; jp++) {
                int cur = jp & 1;
                if (jp < 7)
                    LDSM4T(bvh[cur ^ 1], sS + o0 + (jp + 1) * 32);
                MMA16816H(out[2 * jp],     ah, bvh[cur][0], bvh[cur][1]);
                MMA16816H(out[2 * jp + 1], ah, bvh[cur][2], bvh[cur][3]);
            }
        }
    }

    l0 += __shfl_xor_sync(0xffffffffu, l0, 1);
    l0 += __shfl_xor_sync(0xffffffffu, l0, 2);
    l1 += __shfl_xor_sync(0xffffffffu, l1, 1);
    l1 += __shfl_xor_sync(0xffffffffu, l1, 2);
    float il0 = 1.f / l0, il1 = 1.f / l1;

    int b = bh >> 4, hh = bh & 15;
    int grow0 = b * SEQ + q0 + 16 * w + rq;
    __half* cb0 = g_cxh + (size_t)grow0 * KA + hh * HD + 2 * cq;
    __half* cb1 = cb0 + (size_t)8 * KA;
#pragma unroll
    for (int nt = 0; nt < 16; nt++) {
        *(uint32_t*)(cb0 + nt * 8) = packh(out[nt][0] * il0, out[nt][1] * il0);
        *(uint32_t*)(cb1 + nt * 8) = packh(out[nt][2] * il1, out[nt][3] * il1);
    }
}

// ---------------------------------------------------------------------------
// Launch graph (idx 3 = QKV GEMM w/ fused RoPE-pack epilogue, ncu slot)
// ---------------------------------------------------------------------------
extern "C" void kernel_launch(void* const* d_in, const int* in_sizes, int n_in,
                              void* d_out, int out_size) {
    const float* x    = (const float*)d_in[0];
    // d_in[1] = attn_mask (pure causal) — reproduced analytically, not read
    const float* Wqkv = (const float*)d_in[2];
    const float* Wout = (const float*)d_in[3];
    float* out = (float*)d_out;

    __half *xh = 0, *wqp = 0, *wop = 0, *cxh = 0;
    cudaGetSymbolAddress((void**)&xh,  g_xh);
    cudaGetSymbolAddress((void**)&wqp, g_wqp);
    cudaGetSymbolAddress((void**)&wop, g_wop);
    cudaGetSymbolAddress((void**)&cxh, g_cxh);

    cudaFuncSetAttribute(tc_gemm_kernel,
                         cudaFuncAttributeMaxDynamicSharedMemorySize, GEMM_SMEM);
    cudaFuncSetAttribute(tc_gemm_qkv_kernel,
                         cudaFuncAttributeMaxDynamicSharedMemorySize, GEMM_SMEM);
    cudaFuncSetAttribute(attn_mma_kernel,
                         cudaFuncAttributeMaxDynamicSharedMemorySize, ATTN_SMEM);

    // idx 0: RoPE table (needed by the fused QKV epilogue)
    rope_table_kernel<<<(SEQ * 64 + 255) / 256, 256>>>();
    // idx 1..2: input + Wqkv packs
    pack_x_kernel<<<MROWS * HID / 2048, 256>>>(x, xh, MROWS * HID);
    pack_x_kernel<<<QKVN * HID / 2048, 256>>>(Wqkv, wqp, QKVN * HID);

    // idx 3: QKV GEMM with fused RoPE + fp16 pack epilogue (ncu capture slot)
    tc_gemm_qkv_kernel<<<dim3(QKVN / 128, MROWS / 128), 128, GEMM_SMEM>>>(
        xh, wqp);

    // idx 4: Wout pack (only needed before out-proj)
    pack_x_kernel<<<HID * HID / 2048, 256>>>(Wout, wop, HID * HID);

    // idx 5: attention (fp16 1-pass, LPT grid, fused fp16 ctx epilogue)
    attn_mma_kernel<<<(SEQ / 128) * BATCH * NH, 256, ATTN_SMEM>>>();

    // idx 6: output GEMM (fp32 epilogue to d_out)
    tc_gemm_kernel<<<dim3(HID / 128, MROWS / 128), 128, GEMM_SMEM>>>(
        cxh, wop, out, HID);
}

// round 15
// speedup vs baseline: 1.0094x; 1.0094x over previous
#include <cuda_runtime.h>
#include <cuda_bf16.h>
#include <cuda_fp16.h>
#include <math.h>
#include <stdint.h>

// Problem constants
#define SEQ   2048
#define HID   2048
#define NH    16
#define HD    128
#define BATCH 2
#define MROWS (BATCH * SEQ)     // 4096
#define QKVN  (3 * HID)         // 6144
#define KA    2048              // fp16 row length (single plane)

// ---------------------------------------------------------------------------
// Scratch (device globals — no runtime allocation allowed)
// ---------------------------------------------------------------------------
__device__ __align__(16) float g_cos[SEQ * 64];
__device__ __align__(16) float g_sin[SEQ * 64];
__device__ __align__(16) __half g_xh [(size_t)MROWS * KA];     // x, fp16
__device__ __align__(16) __half g_wqp[(size_t)QKVN  * KA];     // Wqkv fp16
__device__ __align__(16) __half g_wop[(size_t)HID   * KA];     // Wout fp16
__device__ __align__(16) __half g_cxh[(size_t)MROWS * KA];     // ctx, fp16
// attention operands (fp16, single plane each, per-(b,h) planar)
__device__ __align__(16) __half g_qp[(size_t)BATCH * NH * SEQ * HD];
__device__ __align__(16) __half g_kp[(size_t)BATCH * NH * SEQ * HD];
__device__ __align__(16) __half g_vp[(size_t)BATCH * NH * SEQ * HD];

// ---------------------------------------------------------------------------
// PTX helpers (arch-agnostic: cp.async / ldmatrix / mma.sync only)
// ---------------------------------------------------------------------------
__device__ __forceinline__ uint32_t s2u(const void* p) {
    uint32_t a;
    asm("{ .reg .u64 t; cvta.to.shared.u64 t, %1; cvt.u32.u64 %0, t; }"
        : "=r"(a) : "l"(p));
    return a;
}

#define CP_ASYNC16(saddr, gptr) \
    asm volatile("cp.async.cg.shared.global [%0], [%1], 16;" \
                 :: "r"(saddr), "l"(gptr))
#define CP_COMMIT()  asm volatile("cp.async.commit_group;" ::: "memory")
#define CP_WAIT0()   asm volatile("cp.async.wait_group 0;" ::: "memory")
#define CP_WAIT1()   asm volatile("cp.async.wait_group 1;" ::: "memory")

#define LDSM4(r, addr)                                                        \
    asm volatile("ldmatrix.sync.aligned.m8n8.x4.shared.b16 {%0,%1,%2,%3}, [%4];" \
        : "=r"((r)[0]), "=r"((r)[1]), "=r"((r)[2]), "=r"((r)[3]) : "r"(addr))
#define LDSM4T(r, addr)                                                       \
    asm volatile("ldmatrix.sync.aligned.m8n8.x4.trans.shared.b16 {%0,%1,%2,%3}, [%4];" \
        : "=r"((r)[0]), "=r"((r)[1]), "=r"((r)[2]), "=r"((r)[3]) : "r"(addr))

#define MMA16816H(d, a, b0, b1)                                               \
    asm volatile("mma.sync.aligned.m16n8k16.row.col.f32.f16.f16.f32 "         \
        "{%0,%1,%2,%3},{%4,%5,%6,%7},{%8,%9},{%0,%1,%2,%3};"                  \
        : "+f"((d)[0]), "+f"((d)[1]), "+f"((d)[2]), "+f"((d)[3])              \
        : "r"((a)[0]), "r"((a)[1]), "r"((a)[2]), "r"((a)[3]),                 \
          "r"(b0), "r"(b1))

__device__ __forceinline__ float ex2f(float x) {
    float y;
    asm("ex2.approx.ftz.f32 %0, %1;" : "=f"(y) : "f"(x));
    return y;
}
__device__ __forceinline__ uint32_t h2u(__half2 h) {
    return *(uint32_t*)&h;
}
__device__ __forceinline__ uint32_t packh(float lo, float hi) {
    __half2 h = __float22half2_rn(make_float2(lo, hi));
    return h2u(h);
}

// ---------------------------------------------------------------------------
// RoPE table (reference-matching numerics)
// ---------------------------------------------------------------------------
__global__ void rope_table_kernel() {
    int idx = blockIdx.x * blockDim.x + threadIdx.x;
    if (idx >= SEQ * 64) return;
    int s = idx >> 6;
    int j = idx & 63;
    double inv = exp(-((double)j / 64.0) * log(10000.0));
    float  invf = (float)inv;
    float  ang  = (float)s * invf;
    g_cos[idx] = (float)cos((double)ang);
    g_sin[idx] = (float)sin((double)ang);
}

// ---------------------------------------------------------------------------
// Merged fp32 -> fp16 pack: x, Wqkv, Wout in one launch (8 elems/thread)
// ---------------------------------------------------------------------------
#define NCX (MROWS * HID / 8)   // x chunks
#define NCQ (QKVN * HID / 8)    // Wqkv chunks
#define NCO (HID * HID / 8)     // Wout chunks
#define NC_ALL (NCX + NCQ + NCO)

__global__ void pack_all_kernel(const float* __restrict__ X,
                                const float* __restrict__ Wq,
                                const float* __restrict__ Wo) {
    int i = blockIdx.x * 256 + threadIdx.x;
    if (i >= NC_ALL) return;
    const float* src;
    __half* dst;
    int off;
    if (i < NCX)            { src = X;  dst = g_xh;  off = i; }
    else if (i < NCX + NCQ) { src = Wq; dst = g_wqp; off = i - NCX; }
    else                    { src = Wo; dst = g_wop; off = i - NCX - NCQ; }
    size_t e = (size_t)off * 8;
    float4 a = *(const float4*)(src + e);
    float4 b = *(const float4*)(src + e + 4);
    *(uint4*)(dst + e) = make_uint4(
        packh(a.x, a.y), packh(a.z, a.w), packh(b.x, b.y), packh(b.z, b.w));
}

// ---------------------------------------------------------------------------
// Shared GEMM config
// ---------------------------------------------------------------------------
#define AST         72
#define STG_MAT     (128 * AST * 2)
#define STG_BYTES   (2 * STG_MAT)
#define GEMM_STAGES 3
#define GEMM_SMEM   (GEMM_STAGES * STG_BYTES)   // 110592
#define GNITER      32

__device__ __forceinline__ void g_load_stage(
    uint32_t sA, const __half* Ab, const __half* Bb, int tid)
{
#pragma unroll
    for (int t = 0; t < 8; t++) {
        int c = tid + t * 128;
        int r = c >> 3, co = (c & 7) << 3;
        CP_ASYNC16(sA + (r * AST + co) * 2, Ab + (size_t)r * KA + co);
        CP_ASYNC16(sA + STG_MAT + (r * AST + co) * 2, Bb + (size_t)r * KA + co);
    }
}

__device__ __forceinline__ void gemm_mainloop(
    uint32_t smb, const __half* A, const __half* B,
    int m0, int n0, int tid, int lane, int wm, int wn,
    float acc[4][8][4])
{
    uint32_t a_off[4][4], b_off[4][4];
#pragma unroll
    for (int ks = 0; ks < 4; ks++) {
#pragma unroll
        for (int mt = 0; mt < 4; mt++)
            a_off[ks][mt] = ((wm + mt * 16 + (lane & 15)) * AST +
                             ks * 16 + (lane >> 4) * 8) * 2;
#pragma unroll
        for (int np = 0; np < 4; np++)
            b_off[ks][np] = STG_MAT +
                ((wn + np * 16 + ((lane >> 4) & 1) * 8 + (lane & 7)) * AST +
                 ks * 16 + ((lane >> 3) & 1) * 8) * 2;
    }

#pragma unroll
    for (int p = 0; p < GEMM_STAGES - 1; p++) {
        g_load_stage(smb + p * STG_BYTES,
                     A + (size_t)m0 * KA + (p << 6),
                     B + (size_t)n0 * KA + (p << 6), tid);
        CP_COMMIT();
    }
    CP_WAIT1();
    __syncthreads();

    uint32_t af[2][4][4], bf[2][4];
#pragma unroll
    for (int mt = 0; mt < 4; mt++) LDSM4(af[0][mt], smb + a_off[0][mt]);
    LDSM4(bf[0], smb + b_off[0][0]);

    for (int it = 0; it < GNITER; ++it) {
        uint32_t sbase = smb + (it % GEMM_STAGES) * STG_BYTES;

        int nx = it + GEMM_STAGES - 1;
        if (nx < GNITER) {
            g_load_stage(smb + (nx % GEMM_STAGES) * STG_BYTES,
                         A + (size_t)m0 * KA + (nx << 6),
                         B + (size_t)n0 * KA + (nx << 6), tid);
        }
        CP_COMMIT();

#pragma unroll
        for (int ks = 0; ks < 4; ks++) {
            int cur = ks & 1, nxt = cur ^ 1;
            uint32_t bb[2][4];
#pragma unroll
            for (int e = 0; e < 4; e++) bb[0][e] = bf[cur][e];
#pragma unroll
            for (int np = 0; np < 4; np++) {
                if (np < 3) LDSM4(bb[(np + 1) & 1], sbase + b_off[ks][np + 1]);
#pragma unroll
                for (int mt = 0; mt < 4; mt++) {
                    MMA16816H(acc[mt][2 * np],     af[cur][mt], bb[np & 1][0], bb[np & 1][1]);
                    MMA16816H(acc[mt][2 * np + 1], af[cur][mt], bb[np & 1][2], bb[np & 1][3]);
                }
            }
            if (ks < 3) {
#pragma unroll
                for (int mt = 0; mt < 4; mt++)
                    LDSM4(af[nxt][mt], sbase + a_off[ks + 1][mt]);
                LDSM4(bf[nxt], sbase + b_off[ks + 1][0]);
            }
        }

        CP_WAIT1();
        __syncthreads();
        uint32_t nbase = smb + ((it + 1) % GEMM_STAGES) * STG_BYTES;
#pragma unroll
        for (int mt = 0; mt < 4; mt++) LDSM4(af[0][mt], nbase + a_off[0][mt]);
        LDSM4(bf[0], nbase + b_off[0][0]);
    }
}

// ---------------------------------------------------------------------------
// Out-projection GEMM: fp32 epilogue to C
// ---------------------------------------------------------------------------
__global__ void __launch_bounds__(128, 2) tc_gemm_kernel(
    const __half* __restrict__ A, const __half* __restrict__ B,
    float* __restrict__ C, int ldc)
{
    extern __shared__ char smg[];
    uint32_t smb = s2u(smg);
    int tid  = threadIdx.x;
    int lane = tid & 31, wid = tid >> 5;
    int wm = (wid & 1) * 64, wn = (wid >> 1) * 64;
    int m0 = blockIdx.y * 128, n0 = blockIdx.x * 128;

    float acc[4][8][4];
#pragma unroll
    for (int i = 0; i < 4; i++)
#pragma unroll
        for (int j = 0; j < 8; j++)
#pragma unroll
            for (int k = 0; k < 4; k++) acc[i][j][k] = 0.f;

    gemm_mainloop(smb, A, B, m0, n0, tid, lane, wm, wn, acc);

    float* Cb = C + (size_t)(m0 + wm) * ldc + n0 + wn;
    int rq = lane >> 2, cq = (lane & 3) * 2;
#pragma unroll
    for (int mt = 0; mt < 4; mt++)
#pragma unroll
        for (int nt = 0; nt < 8; nt++) {
            *(float2*)(Cb + (size_t)(mt * 16 + rq) * ldc + nt * 8 + cq) =
                make_float2(acc[mt][nt][0], acc[mt][nt][1]);
            *(float2*)(Cb + (size_t)(mt * 16 + rq + 8) * ldc + nt * 8 + cq) =
                make_float2(acc[mt][nt][2], acc[mt][nt][3]);
        }
}

// ---------------------------------------------------------------------------
// QKV GEMM with fused RoPE + fp16 pack epilogue (unchanged from R14)
// ---------------------------------------------------------------------------
#define EP_STR 132

__global__ void __launch_bounds__(128, 2) tc_gemm_qkv_kernel(
    const __half* __restrict__ A, const __half* __restrict__ B)
{
    extern __shared__ char smg[];
    uint32_t smb = s2u(smg);
    int tid  = threadIdx.x;
    int lane = tid & 31, wid = tid >> 5;
    int wm = (wid & 1) * 64, wn = (wid >> 1) * 64;
    int m0 = blockIdx.y * 128, n0 = blockIdx.x * 128;

    float acc[4][8][4];
#pragma unroll
    for (int i = 0; i < 4; i++)
#pragma unroll
        for (int j = 0; j < 8; j++)
#pragma unroll
            for (int k = 0; k < 4; k++) acc[i][j][k] = 0.f;

    gemm_mainloop(smb, A, B, m0, n0, tid, lane, wm, wn, acc);

    __syncthreads();
    float* st = (float*)smg;
    int rq = lane >> 2, cq2 = (lane & 3) * 2;
#pragma unroll
    for (int mt = 0; mt < 4; mt++)
#pragma unroll
        for (int nt = 0; nt < 8; nt++) {
            int c = wn + nt * 8 + cq2;
            *(float2*)&st[(wm + mt * 16 + rq) * EP_STR + c] =
                make_float2(acc[mt][nt][0], acc[mt][nt][1]);
            *(float2*)&st[(wm + mt * 16 + rq + 8) * EP_STR + c] =
                make_float2(acc[mt][nt][2], acc[mt][nt][3]);
        }
    __syncthreads();

    int region = n0 >> 11;           // 0:q 1:k 2:v
    int head   = (n0 & 2047) >> 7;

    if (region < 2) {
        __half* dst = (region == 0) ? g_qp : g_kp;
        for (int t = tid; t < 2048; t += 128) {
            int r  = t >> 4;
            int jg = (t & 15) << 2;
            int gr = m0 + r;
            int s  = gr & (SEQ - 1);
            int bh = (gr >> 11) * NH + head;
            float4 S1 = *(float4*)&st[r * EP_STR + jg];
            float4 S2 = *(float4*)&st[r * EP_STR + jg + 64];
            float4 c4 = *(const float4*)&g_cos[(s << 6) + jg];
            float4 s4 = *(const float4*)&g_sin[(s << 6) + jg];
            float a0 = S1.x * c4.x - S2.x * s4.x;
            float a1 = S1.y * c4.y - S2.y * s4.y;
            float a2 = S1.z * c4.z - S2.z * s4.z;
            float a3 = S1.w * c4.w - S2.w * s4.w;
            float b0 = S2.x * c4.x + S1.x * s4.x;
            float b1 = S2.y * c4.y + S1.y * s4.y;
            float b2 = S2.z * c4.z + S1.z * s4.z;
            float b3 = S2.w * c4.w + S1.w * s4.w;
            size_t base = ((size_t)bh * SEQ + s) * HD;
            *(uint2*)(dst + base + jg) =
                make_uint2(packh(a0, a1), packh(a2, a3));
            *(uint2*)(dst + base + jg + 64) =
                make_uint2(packh(b0, b1), packh(b2, b3));
        }
    } else {
        for (int t = tid; t < 2048; t += 128) {
            int r  = t >> 4;
            int jg = (t & 15) << 3;
            int gr = m0 + r;
            int s  = gr & (SEQ - 1);
            int bh = (gr >> 11) * NH + head;
            float4 a = *(float4*)&st[r * EP_STR + jg];
            float4 b = *(float4*)&st[r * EP_STR + jg + 4];
            size_t base = ((size_t)bh * SEQ + s) * HD;
            *(uint4*)(g_vp + base + jg) = make_uint4(
                packh(a.x, a.y), packh(a.z, a.w),
                packh(b.x, b.y), packh(b.z, b.w));
        }
    }
}

// ---------------------------------------------------------------------------
// Tensor-core flash attention v6: fp16 1-pass, BK=128 K-tiles, 2-slot KV ring,
// Q register-resident, causal, online softmax, LPT grid, fused fp16 ctx
// epilogue.
// ---------------------------------------------------------------------------
#define AKST     136
#define AROWB    (AKST * 2)                 // 272 B
#define KVP2     (128 * AROWB)              // 34816 (one 128-row plane)
#define STG2_B   (2 * KVP2)                 // 69632 (K + V tile)
#define ATTN_SMEM (2 * STG2_B + KVP2)       // 174080

__device__ __forceinline__ void load_kv128(
    uint32_t dst, const __half* Kp, const __half* Vp, int k0, int tid)
{
#pragma unroll
    for (int t = 0; t < 16; t++) {
        int c = tid + t * 256;              // 0..4095
        int plane = c >> 11;                // 0:K 1:V
        int r = (c >> 4) & 127;
        int co = c & 15;
        const __half* src = (plane == 0)
            ? Kp + ((size_t)k0 + r) * HD + co * 8
            : Vp + ((size_t)k0 + r) * HD + co * 8;
        CP_ASYNC16(dst + plane * KVP2 + r * AROWB + co * 16, src);
    }
}

__global__ void __launch_bounds__(256) attn_mma_kernel() {
    extern __shared__ char sma[];
    uint32_t smb = s2u(sma);
    int tid = threadIdx.x, lane = tid & 31, w = tid >> 5;
    int qt = 15 - ((int)blockIdx.x >> 5);   // LPT: heaviest first
    int bh = (int)blockIdx.x & 31;
    int q0 = qt * 128;
    int nkt = qt + 1;                       // BK=128 tiles

    const __half* Qp = g_qp + (size_t)bh * SEQ * HD;
    const __half* Kp = g_kp + (size_t)bh * SEQ * HD;
    const __half* Vp = g_vp + (size_t)bh * SEQ * HD;

    // prologue: Q (g0) into dedicated stage; s0 (g1) into slot 0
    uint32_t sQstage = smb + 2 * STG2_B;
#pragma unroll
    for (int t = 0; t < 8; t++) {
        int c = tid + t * 256;
        int r = c >> 4, co = c & 15;
        CP_ASYNC16(sQstage + r * AROWB + co * 16,
                   Qp + ((size_t)q0 + r) * HD + co * 8);
    }
    CP_COMMIT();
    load_kv128(smb, Kp, Vp, 0, tid);
    CP_COMMIT();

    int rq = lane >> 2, cq = lane & 3;
    uint32_t qoff = (uint32_t)(16 * w + (lane & 15)) * AROWB + ((lane >> 4) & 1) * 16;
    uint32_t koff = (uint32_t)(((lane >> 4) & 1) * 8 + (lane & 7)) * AROWB +
                    ((lane >> 3) & 1) * 16;
    uint32_t voff = KVP2 +
                    (uint32_t)(((lane >> 3) & 1) * 8 + (lane & 7)) * AROWB +
                    ((lane >> 4) & 1) * 16;

    // Q fragments -> registers (g0 done when <=1 group pending)
    CP_WAIT1();
    __syncthreads();
    uint32_t qfh[8][4];
#pragma unroll
    for (int kc = 0; kc < 8; kc++)
        LDSM4(qfh[kc], sQstage + qoff + kc * 32);

    float out[16][4];
#pragma unroll
    for (int n = 0; n < 16; n++)
#pragma unroll
        for (int e = 0; e < 4; e++) out[n][e] = 0.f;
    float m0 = -1e30f, m1 = -1e30f, l0 = 0.f, l1 = 0.f;

    const float SCALE2 = 0.08838834764831845f * 1.44269504088896341f;

    for (int kt = 0; kt < nkt; kt++) {
        CP_WAIT0();             // s_kt resident (its load overlapped iter kt-1)
        __syncthreads();        // all warps done with slot (kt+1)&1 from iter kt-1
        if (kt + 1 < nkt)
            load_kv128(smb + ((kt + 1) & 1) * STG2_B, Kp, Vp,
                       (kt + 1) * 128, tid);
        CP_COMMIT();

        uint32_t sS = smb + (kt & 1) * STG2_B;   // K at +0, V at +KVP2

        // ---- scores: S[128 x 128] = Q*K^T (double-buffered K frags) ----
        float sc[16][4];
#pragma unroll
        for (int j = 0; j < 16; j++)
#pragma unroll
            for (int e = 0; e < 4; e++) sc[j][e] = 0.f;

        {
            uint32_t bkh[2][4];
            LDSM4(bkh[0], sS + koff);
#pragma unroll
            for (int t = 0; t < 64; t++) {
                int kc = t >> 3, jj = t & 7;
                int cur = t & 1;
                if (t < 63) {
                    int tn = t + 1;
                    uint32_t on = koff + (uint32_t)(tn & 7) * (16 * AROWB) +
                                  (tn >> 3) * 32;
                    LDSM4(bkh[cur ^ 1], sS + on);
                }
                MMA16816H(sc[2 * jj],     qfh[kc], bkh[cur][0], bkh[cur][1]);
                MMA16816H(sc[2 * jj + 1], qfh[kc], bkh[cur][2], bkh[cur][3]);
            }
        }

        int k0 = kt * 128;
#pragma unroll
        for (int j = 0; j < 16; j++)
#pragma unroll
            for (int e = 0; e < 4; e++) sc[j][e] *= SCALE2;
        if (kt == qt) {         // diagonal tile
            int rg0 = q0 + 16 * w + rq, rg1 = rg0 + 8;
#pragma unroll
            for (int j = 0; j < 16; j++) {
                int cg = k0 + 8 * j + 2 * cq;
                if (cg     > rg0) sc[j][0] = -1e30f;
                if (cg + 1 > rg0) sc[j][1] = -1e30f;
                if (cg     > rg1) sc[j][2] = -1e30f;
                if (cg + 1 > rg1) sc[j][3] = -1e30f;
            }
        }

        float t0 = -1e30f, t1 = -1e30f;
#pragma unroll
        for (int j = 0; j < 16; j++) {
            t0 = fmaxf(t0, fmaxf(sc[j][0], sc[j][1]));
            t1 = fmaxf(t1, fmaxf(sc[j][2], sc[j][3]));
        }
        t0 = fmaxf(t0, __shfl_xor_sync(0xffffffffu, t0, 1));
        t0 = fmaxf(t0, __shfl_xor_sync(0xffffffffu, t0, 2));
        t1 = fmaxf(t1, __shfl_xor_sync(0xffffffffu, t1, 1));
        t1 = fmaxf(t1, __shfl_xor_sync(0xffffffffu, t1, 2));
        float mn0 = fmaxf(m0, t0), mn1 = fmaxf(m1, t1);
        float al0 = ex2f(m0 - mn0), al1 = ex2f(m1 - mn1);
        m0 = mn0; m1 = mn1;
        l0 *= al0; l1 *= al1;
#pragma unroll
        for (int n = 0; n < 16; n++) {
            out[n][0] *= al0; out[n][1] *= al0;
            out[n][2] *= al1; out[n][3] *= al1;
        }

        // ---- exp + PV over 8 P-chunks of 16 (double-buffered V frags) ----
#pragma unroll
        for (int kc = 0; kc < 8; kc++) {
            int j0 = 2 * kc, j1 = 2 * kc + 1;
            float p00 = ex2f(sc[j0][0] - m0), p01 = ex2f(sc[j0][1] - m0);
            float p02 = ex2f(sc[j0][2] - m1), p03 = ex2f(sc[j0][3] - m1);
            float p10 = ex2f(sc[j1][0] - m0), p11 = ex2f(sc[j1][1] - m0);
            float p12 = ex2f(sc[j1][2] - m1), p13 = ex2f(sc[j1][3] - m1);
            l0 += p00 + p01 + p10 + p11;
            l1 += p02 + p03 + p12 + p13;

            uint32_t ah[4];
            ah[0] = packh(p00, p01);
            ah[1] = packh(p02, p03);
            ah[2] = packh(p10, p11);
            ah[3] = packh(p12, p13);

            uint32_t bvh[2][4];
            uint32_t o0 = voff + (uint32_t)kc * (16 * AROWB);
            LDSM4T(bvh[0], sS + o0);
#pragma unroll
            for (int jp = 0; jp < 8; jp++) {
                int cur = jp & 1;
                if (jp < 7)
                    LDSM4T(bvh[cur ^ 1], sS + o0 + (jp + 1) * 32);
                MMA16816H(out[2 * jp],     ah, bvh[cur][0], bvh[cur][1]);
                MMA16816H(out[2 * jp + 1], ah, bvh[cur][2], bvh[cur][3]);
            }
        }
    }

    l0 += __shfl_xor_sync(0xffffffffu, l0, 1);
    l0 += __shfl_xor_sync(0xffffffffu, l0, 2);
    l1 += __shfl_xor_sync(0xffffffffu, l1, 1);
    l1 += __shfl_xor_sync(0xffffffffu, l1, 2);
    float il0 = 1.f / l0, il1 = 1.f / l1;

    int b = bh >> 4, hh = bh & 15;
    int grow0 = b * SEQ + q0 + 16 * w + rq;
    __half* cb0 = g_cxh + (size_t)grow0 * KA + hh * HD + 2 * cq;
    __half* cb1 = cb0 + (size_t)8 * KA;
#pragma unroll
    for (int nt = 0; nt < 16; nt++) {
        *(uint32_t*)(cb0 + nt * 8) = packh(out[nt][0] * il0, out[nt][1] * il0);
        *(uint32_t*)(cb1 + nt * 8) = packh(out[nt][2] * il1, out[nt][3] * il1);
    }
}

// ---------------------------------------------------------------------------
// Launch graph (5 launches)
// ---------------------------------------------------------------------------
extern "C" void kernel_launch(void* const* d_in, const int* in_sizes, int n_in,
                              void* d_out, int out_size) {
    const float* x    = (const float*)d_in[0];
    // d_in[1] = attn_mask (pure causal) — reproduced analytically, not read
    const float* Wqkv = (const float*)d_in[2];
    const float* Wout = (const float*)d_in[3];
    float* out = (float*)d_out;

    __half *xh = 0, *wqp = 0, *wop = 0, *cxh = 0;
    cudaGetSymbolAddress((void**)&xh,  g_xh);
    cudaGetSymbolAddress((void**)&wqp, g_wqp);
    cudaGetSymbolAddress((void**)&wop, g_wop);
    cudaGetSymbolAddress((void**)&cxh, g_cxh);

    cudaFuncSetAttribute(tc_gemm_kernel,
                         cudaFuncAttributeMaxDynamicSharedMemorySize, GEMM_SMEM);
    cudaFuncSetAttribute(tc_gemm_qkv_kernel,
                         cudaFuncAttributeMaxDynamicSharedMemorySize, GEMM_SMEM);
    cudaFuncSetAttribute(attn_mma_kernel,
                         cudaFuncAttributeMaxDynamicSharedMemorySize, ATTN_SMEM);

    // idx 0: RoPE table
    rope_table_kernel<<<(SEQ * 64 + 255) / 256, 256>>>();
    // idx 1: merged packs (x + Wqkv + Wout)
    pack_all_kernel<<<(NC_ALL + 255) / 256, 256>>>(x, Wqkv, Wout);
    // idx 2: QKV GEMM with fused RoPE + fp16 pack epilogue
    tc_gemm_qkv_kernel<<<dim3(QKVN / 128, MROWS / 128), 128, GEMM_SMEM>>>(
        xh, wqp);
    // idx 3: attention (fp16 1-pass, BK=128, LPT grid, fused ctx epilogue)
    attn_mma_kernel<<<(SEQ / 128) * BATCH * NH, 256, ATTN_SMEM>>>();
    // idx 4: output GEMM
    tc_gemm_kernel<<<dim3(HID / 128, MROWS / 128), 128, GEMM_SMEM>>>(
        cxh, wop, out, HID);
}

// round 16
// speedup vs baseline: 1.0103x; 1.0010x over previous
#include <cuda_runtime.h>
#include <cuda_bf16.h>
#include <cuda_fp16.h>
#include <math.h>
#include <stdint.h>

// Problem constants
#define SEQ   2048
#define HID   2048
#define NH    16
#define HD    128
#define BATCH 2
#define MROWS (BATCH * SEQ)     // 4096
#define QKVN  (3 * HID)         // 6144
#define KA    2048              // fp16 row length (single plane)

// ---------------------------------------------------------------------------
// Scratch (device globals — no runtime allocation allowed)
// ---------------------------------------------------------------------------
__device__ __align__(16) float g_cos[SEQ * 64];
__device__ __align__(16) float g_sin[SEQ * 64];
__device__ __align__(16) __half g_xh [(size_t)MROWS * KA];     // x, fp16
__device__ __align__(16) __half g_wqp[(size_t)QKVN  * KA];     // Wqkv fp16
__device__ __align__(16) __half g_wop[(size_t)HID   * KA];     // Wout fp16
__device__ __align__(16) __half g_cxh[(size_t)MROWS * KA];     // ctx, fp16
// attention operands (fp16, single plane each, per-(b,h) planar)
__device__ __align__(16) __half g_qp[(size_t)BATCH * NH * SEQ * HD];
__device__ __align__(16) __half g_kp[(size_t)BATCH * NH * SEQ * HD];
__device__ __align__(16) __half g_vp[(size_t)BATCH * NH * SEQ * HD];

// ---------------------------------------------------------------------------
// PTX helpers (arch-agnostic: cp.async / ldmatrix / mma.sync only)
// ---------------------------------------------------------------------------
__device__ __forceinline__ uint32_t s2u(const void* p) {
    uint32_t a;
    asm("{ .reg .u64 t; cvta.to.shared.u64 t, %1; cvt.u32.u64 %0, t; }"
        : "=r"(a) : "l"(p));
    return a;
}

#define CP_ASYNC16(saddr, gptr) \
    asm volatile("cp.async.cg.shared.global [%0], [%1], 16;" \
                 :: "r"(saddr), "l"(gptr))
#define CP_COMMIT()  asm volatile("cp.async.commit_group;" ::: "memory")
#define CP_WAIT1()   asm volatile("cp.async.wait_group 1;" ::: "memory")
#define CP_WAIT2()   asm volatile("cp.async.wait_group 2;" ::: "memory")

#define LDSM4(r, addr)                                                        \
    asm volatile("ldmatrix.sync.aligned.m8n8.x4.shared.b16 {%0,%1,%2,%3}, [%4];" \
        : "=r"((r)[0]), "=r"((r)[1]), "=r"((r)[2]), "=r"((r)[3]) : "r"(addr))
#define LDSM4T(r, addr)                                                       \
    asm volatile("ldmatrix.sync.aligned.m8n8.x4.trans.shared.b16 {%0,%1,%2,%3}, [%4];" \
        : "=r"((r)[0]), "=r"((r)[1]), "=r"((r)[2]), "=r"((r)[3]) : "r"(addr))

#define MMA16816H(d, a, b0, b1)                                               \
    asm volatile("mma.sync.aligned.m16n8k16.row.col.f32.f16.f16.f32 "         \
        "{%0,%1,%2,%3},{%4,%5,%6,%7},{%8,%9},{%0,%1,%2,%3};"                  \
        : "+f"((d)[0]), "+f"((d)[1]), "+f"((d)[2]), "+f"((d)[3])              \
        : "r"((a)[0]), "r"((a)[1]), "r"((a)[2]), "r"((a)[3]),                 \
          "r"(b0), "r"(b1))

__device__ __forceinline__ float ex2f(float x) {
    float y;
    asm("ex2.approx.ftz.f32 %0, %1;" : "=f"(y) : "f"(x));
    return y;
}
__device__ __forceinline__ uint32_t h2u(__half2 h) {
    return *(uint32_t*)&h;
}
__device__ __forceinline__ uint32_t packh(float lo, float hi) {
    __half2 h = __float22half2_rn(make_float2(lo, hi));
    return h2u(h);
}

// ---------------------------------------------------------------------------
// Merged prep: fp32 -> fp16 packs (x, Wqkv, Wout) + RoPE table, one launch.
// ---------------------------------------------------------------------------
#define NCX (MROWS * HID / 8)
#define NCQ (QKVN * HID / 8)
#define NCO (HID * HID / 8)
#define NC_ALL (NCX + NCQ + NCO)
#define NROPE (SEQ * 64)
#define NPREP (NC_ALL + NROPE)

__global__ void prep_kernel(const float* __restrict__ X,
                            const float* __restrict__ Wq,
                            const float* __restrict__ Wo) {
    int i = blockIdx.x * 256 + threadIdx.x;
    if (i >= NPREP) return;
    if (i >= NC_ALL) {
        int idx = i - NC_ALL;
        int s = idx >> 6;
        int j = idx & 63;
        double inv = exp(-((double)j / 64.0) * log(10000.0));
        float  invf = (float)inv;
        float  ang  = (float)s * invf;
        g_cos[idx] = (float)cos((double)ang);
        g_sin[idx] = (float)sin((double)ang);
        return;
    }
    const float* src;
    __half* dst;
    int off;
    if (i < NCX)            { src = X;  dst = g_xh;  off = i; }
    else if (i < NCX + NCQ) { src = Wq; dst = g_wqp; off = i - NCX; }
    else                    { src = Wo; dst = g_wop; off = i - NCX - NCQ; }
    size_t e = (size_t)off * 8;
    float4 a = *(const float4*)(src + e);
    float4 b = *(const float4*)(src + e + 4);
    *(uint4*)(dst + e) = make_uint4(
        packh(a.x, a.y), packh(a.z, a.w), packh(b.x, b.y), packh(b.z, b.w));
}

// ---------------------------------------------------------------------------
// Shared GEMM config
// ---------------------------------------------------------------------------
#define AST         72
#define STG_MAT     (128 * AST * 2)
#define STG_BYTES   (2 * STG_MAT)
#define GEMM_STAGES 3
#define GEMM_SMEM   (GEMM_STAGES * STG_BYTES)   // 110592
#define GNITER      32

__device__ __forceinline__ void g_load_stage(
    uint32_t sA, const __half* Ab, const __half* Bb, int tid)
{
#pragma unroll
    for (int t = 0; t < 8; t++) {
        int c = tid + t * 128;
        int r = c >> 3, co = (c & 7) << 3;
        CP_ASYNC16(sA + (r * AST + co) * 2, Ab + (size_t)r * KA + co);
        CP_ASYNC16(sA + STG_MAT + (r * AST + co) * 2, Bb + (size_t)r * KA + co);
    }
}

__device__ __forceinline__ void gemm_mainloop(
    uint32_t smb, const __half* A, const __half* B,
    int m0, int n0, int tid, int lane, int wm, int wn,
    float acc[4][8][4])
{
    uint32_t a_off[4][4], b_off[4][4];
#pragma unroll
    for (int ks = 0; ks < 4; ks++) {
#pragma unroll
        for (int mt = 0; mt < 4; mt++)
            a_off[ks][mt] = ((wm + mt * 16 + (lane & 15)) * AST +
                             ks * 16 + (lane >> 4) * 8) * 2;
#pragma unroll
        for (int np = 0; np < 4; np++)
            b_off[ks][np] = STG_MAT +
                ((wn + np * 16 + ((lane >> 4) & 1) * 8 + (lane & 7)) * AST +
                 ks * 16 + ((lane >> 3) & 1) * 8) * 2;
    }

#pragma unroll
    for (int p = 0; p < GEMM_STAGES - 1; p++) {
        g_load_stage(smb + p * STG_BYTES,
                     A + (size_t)m0 * KA + (p << 6),
                     B + (size_t)n0 * KA + (p << 6), tid);
        CP_COMMIT();
    }
    CP_WAIT1();
    __syncthreads();

    uint32_t af[2][4][4], bf[2][4];
#pragma unroll
    for (int mt = 0; mt < 4; mt++) LDSM4(af[0][mt], smb + a_off[0][mt]);
    LDSM4(bf[0], smb + b_off[0][0]);

    for (int it = 0; it < GNITER; ++it) {
        uint32_t sbase = smb + (it % GEMM_STAGES) * STG_BYTES;

        int nx = it + GEMM_STAGES - 1;
        if (nx < GNITER) {
            g_load_stage(smb + (nx % GEMM_STAGES) * STG_BYTES,
                         A + (size_t)m0 * KA + (nx << 6),
                         B + (size_t)n0 * KA + (nx << 6), tid);
        }
        CP_COMMIT();

#pragma unroll
        for (int ks = 0; ks < 4; ks++) {
            int cur = ks & 1, nxt = cur ^ 1;
            uint32_t bb[2][4];
#pragma unroll
            for (int e = 0; e < 4; e++) bb[0][e] = bf[cur][e];
#pragma unroll
            for (int np = 0; np < 4; np++) {
                if (np < 3) LDSM4(bb[(np + 1) & 1], sbase + b_off[ks][np + 1]);
#pragma unroll
                for (int mt = 0; mt < 4; mt++) {
                    MMA16816H(acc[mt][2 * np],     af[cur][mt], bb[np & 1][0], bb[np & 1][1]);
                    MMA16816H(acc[mt][2 * np + 1], af[cur][mt], bb[np & 1][2], bb[np & 1][3]);
                }
            }
            if (ks < 3) {
#pragma unroll
                for (int mt = 0; mt < 4; mt++)
                    LDSM4(af[nxt][mt], sbase + a_off[ks + 1][mt]);
                LDSM4(bf[nxt], sbase + b_off[ks + 1][0]);
            }
        }

        CP_WAIT1();
        __syncthreads();
        uint32_t nbase = smb + ((it + 1) % GEMM_STAGES) * STG_BYTES;
#pragma unroll
        for (int mt = 0; mt < 4; mt++) LDSM4(af[0][mt], nbase + a_off[0][mt]);
        LDSM4(bf[0], nbase + b_off[0][0]);
    }
}

// ---------------------------------------------------------------------------
// Out-projection GEMM: fp32 epilogue to C
// ---------------------------------------------------------------------------
__global__ void __launch_bounds__(128, 2) tc_gemm_kernel(
    const __half* __restrict__ A, const __half* __restrict__ B,
    float* __restrict__ C, int ldc)
{
    extern __shared__ char smg[];
    uint32_t smb = s2u(smg);
    int tid  = threadIdx.x;
    int lane = tid & 31, wid = tid >> 5;
    int wm = (wid & 1) * 64, wn = (wid >> 1) * 64;
    int m0 = blockIdx.y * 128, n0 = blockIdx.x * 128;

    float acc[4][8][4];
#pragma unroll
    for (int i = 0; i < 4; i++)
#pragma unroll
        for (int j = 0; j < 8; j++)
#pragma unroll
            for (int k = 0; k < 4; k++) acc[i][j][k] = 0.f;

    gemm_mainloop(smb, A, B, m0, n0, tid, lane, wm, wn, acc);

    float* Cb = C + (size_t)(m0 + wm) * ldc + n0 + wn;
    int rq = lane >> 2, cq = (lane & 3) * 2;
#pragma unroll
    for (int mt = 0; mt < 4; mt++)
#pragma unroll
        for (int nt = 0; nt < 8; nt++) {
            *(float2*)(Cb + (size_t)(mt * 16 + rq) * ldc + nt * 8 + cq) =
                make_float2(acc[mt][nt][0], acc[mt][nt][1]);
            *(float2*)(Cb + (size_t)(mt * 16 + rq + 8) * ldc + nt * 8 + cq) =
                make_float2(acc[mt][nt][2], acc[mt][nt][3]);
        }
}

// ---------------------------------------------------------------------------
// QKV GEMM with fused RoPE + fp16 pack epilogue (unchanged from R14/R15)
// ---------------------------------------------------------------------------
#define EP_STR 132

__global__ void __launch_bounds__(128, 2) tc_gemm_qkv_kernel(
    const __half* __restrict__ A, const __half* __restrict__ B)
{
    extern __shared__ char smg[];
    uint32_t smb = s2u(smg);
    int tid  = threadIdx.x;
    int lane = tid & 31, wid = tid >> 5;
    int wm = (wid & 1) * 64, wn = (wid >> 1) * 64;
    int m0 = blockIdx.y * 128, n0 = blockIdx.x * 128;

    float acc[4][8][4];
#pragma unroll
    for (int i = 0; i < 4; i++)
#pragma unroll
        for (int j = 0; j < 8; j++)
#pragma unroll
            for (int k = 0; k < 4; k++) acc[i][j][k] = 0.f;

    gemm_mainloop(smb, A, B, m0, n0, tid, lane, wm, wn, acc);

    __syncthreads();
    float* st = (float*)smg;
    int rq = lane >> 2, cq2 = (lane & 3) * 2;
#pragma unroll
    for (int mt = 0; mt < 4; mt++)
#pragma unroll
        for (int nt = 0; nt < 8; nt++) {
            int c = wn + nt * 8 + cq2;
            *(float2*)&st[(wm + mt * 16 + rq) * EP_STR + c] =
                make_float2(acc[mt][nt][0], acc[mt][nt][1]);
            *(float2*)&st[(wm + mt * 16 + rq + 8) * EP_STR + c] =
                make_float2(acc[mt][nt][2], acc[mt][nt][3]);
        }
    __syncthreads();

    int region = n0 >> 11;           // 0:q 1:k 2:v
    int head   = (n0 & 2047) >> 7;

    if (region < 2) {
        __half* dst = (region == 0) ? g_qp : g_kp;
        for (int t = tid; t < 2048; t += 128) {
            int r  = t >> 4;
            int jg = (t & 15) << 2;
            int gr = m0 + r;
            int s  = gr & (SEQ - 1);
            int bh = (gr >> 11) * NH + head;
            float4 S1 = *(float4*)&st[r * EP_STR + jg];
            float4 S2 = *(float4*)&st[r * EP_STR + jg + 64];
            float4 c4 = *(const float4*)&g_cos[(s << 6) + jg];
            float4 s4 = *(const float4*)&g_sin[(s << 6) + jg];
            float a0 = S1.x * c4.x - S2.x * s4.x;
            float a1 = S1.y * c4.y - S2.y * s4.y;
            float a2 = S1.z * c4.z - S2.z * s4.z;
            float a3 = S1.w * c4.w - S2.w * s4.w;
            float b0 = S2.x * c4.x + S1.x * s4.x;
            float b1 = S2.y * c4.y + S1.y * s4.y;
            float b2 = S2.z * c4.z + S1.z * s4.z;
            float b3 = S2.w * c4.w + S1.w * s4.w;
            size_t base = ((size_t)bh * SEQ + s) * HD;
            *(uint2*)(dst + base + jg) =
                make_uint2(packh(a0, a1), packh(a2, a3));
            *(uint2*)(dst + base + jg + 64) =
                make_uint2(packh(b0, b1), packh(b2, b3));
        }
    } else {
        for (int t = tid; t < 2048; t += 128) {
            int r  = t >> 4;
            int jg = (t & 15) << 3;
            int gr = m0 + r;
            int s  = gr & (SEQ - 1);
            int bh = (gr >> 11) * NH + head;
            float4 a = *(float4*)&st[r * EP_STR + jg];
            float4 b = *(float4*)&st[r * EP_STR + jg + 4];
            size_t base = ((size_t)bh * SEQ + s) * HD;
            *(uint4*)(g_vp + base + jg) = make_uint4(
                packh(a.x, a.y), packh(a.z, a.w),
                packh(b.x, b.y), packh(b.z, b.w));
        }
    }
}

// ---------------------------------------------------------------------------
// Tensor-core flash attention v7: fp16 1-pass, 128-thread CTAs (2 CTAs/SM),
// 64-row q-tiles, BK=64, 3-slot ring with Q borrowing slot 2, causal,
// online softmax, LPT grid, fused fp16 ctx epilogue.
// ---------------------------------------------------------------------------
#define AKST     136
#define AROWB    (AKST * 2)                 // 272 B
#define KVPLANE  (64 * AROWB)               // 17408 (64-row plane)
#define SLOT_B   (2 * KVPLANE)              // 34816 (K + V)
#define ATTN_SMEM (3 * SLOT_B)              // 104448 -> 2 CTAs/SM

__device__ __forceinline__ void load_kv_stage(
    uint32_t dst, const __half* Kp, const __half* Vp, int k0, int tid)
{
#pragma unroll
    for (int t = 0; t < 16; t++) {
        int c = tid + t * 128;              // 0..2047
        int plane = c >> 10;                // 0:K 1:V
        int r = (c >> 4) & 63;
        int co = c & 15;
        const __half* src = (plane == 0)
            ? Kp + ((size_t)k0 + r) * HD + co * 8
            : Vp + ((size_t)k0 + r) * HD + co * 8;
        CP_ASYNC16(dst + plane * KVPLANE + r * AROWB + co * 16, src);
    }
}

__global__ void __launch_bounds__(128, 2) attn_mma_kernel() {
    extern __shared__ char sma[];
    uint32_t smb = s2u(sma);
    int tid = threadIdx.x, lane = tid & 31, w = tid >> 5;
    int qt = 31 - ((int)blockIdx.x >> 5);   // LPT: heaviest first (64-row tiles)
    int bh = (int)blockIdx.x & 31;
    int q0 = qt * 64;
    int nkt = qt + 1;                       // BK=64 tiles

    const __half* Qp = g_qp + (size_t)bh * SEQ * HD;
    const __half* Kp = g_kp + (size_t)bh * SEQ * HD;
    const __half* Vp = g_vp + (size_t)bh * SEQ * HD;

    // prologue: g0 = Q (64 rows) into slot 2; g1 = s0 -> slot0; g2 = s1 -> slot1
    uint32_t sQstage = smb + 2 * SLOT_B;
#pragma unroll
    for (int t = 0; t < 8; t++) {
        int c = tid + t * 128;              // 0..1023
        int r = c >> 4, co = c & 15;
        CP_ASYNC16(sQstage + r * AROWB + co * 16,
                   Qp + ((size_t)q0 + r) * HD + co * 8);
    }
    CP_COMMIT();
    load_kv_stage(smb, Kp, Vp, 0, tid);
    CP_COMMIT();
    load_kv_stage(smb + SLOT_B, Kp, Vp, 64, tid);   // prefetch (always valid mem)
    CP_COMMIT();

    int rq = lane >> 2, cq = lane & 3;
    uint32_t qoff = (uint32_t)(16 * w + (lane & 15)) * AROWB + ((lane >> 4) & 1) * 16;
    uint32_t koff = (uint32_t)(((lane >> 4) & 1) * 8 + (lane & 7)) * AROWB +
                    ((lane >> 3) & 1) * 16;
    uint32_t voff = KVPLANE +
                    (uint32_t)(((lane >> 3) & 1) * 8 + (lane & 7)) * AROWB +
                    ((lane >> 4) & 1) * 16;

    // Q fragments -> registers (g0 retired when <=2 groups outstanding)
    CP_WAIT2();
    __syncthreads();
    uint32_t qfh[8][4];
#pragma unroll
    for (int kc = 0; kc < 8; kc++)
        LDSM4(qfh[kc], sQstage + qoff + kc * 32);

    float out[16][4];
#pragma unroll
    for (int n = 0; n < 16; n++)
#pragma unroll
        for (int e = 0; e < 4; e++) out[n][e] = 0.f;
    float m0 = -1e30f, m1 = -1e30f, l0 = 0.f, l1 = 0.f;

    const float SCALE2 = 0.08838834764831845f * 1.44269504088896341f;

    // stage kt = group kt+1; at iter kt, WAIT1 drains group kt+1 (s_kt ready)
    // while leaving s_{kt+1} in flight. The sync also guarantees all warps
    // finished Q-frag reads before slot 2 is overwritten at kt=0.
    for (int kt = 0; kt < nkt; kt++) {
        CP_WAIT1();
        __syncthreads();
        if (kt + 2 < nkt)
            load_kv_stage(smb + ((kt + 2) % 3) * SLOT_B, Kp, Vp,
                          (kt + 2) * 64, tid);
        CP_COMMIT();

        uint32_t sS = smb + (kt % 3) * SLOT_B;   // K at +0, V at +KVPLANE

        // ---- scores: S[64 x 64] per warp m16 (double-buffered K frags) ----
        float sc[8][4];
#pragma unroll
        for (int j = 0; j < 8; j++)
#pragma unroll
            for (int e = 0; e < 4; e++) sc[j][e] = 0.f;

        {
            uint32_t bkh[2][4];
            LDSM4(bkh[0], sS + koff);
#pragma unroll
            for (int t = 0; t < 32; t++) {
                int kc = t >> 2, jj = t & 3;
                int cur = t & 1;
                if (t < 31) {
                    int tn = t + 1;
                    uint32_t on = koff + (uint32_t)(tn & 3) * (16 * AROWB) +
                                  (tn >> 2) * 32;
                    LDSM4(bkh[cur ^ 1], sS + on);
                }
                MMA16816H(sc[2 * jj],     qfh[kc], bkh[cur][0], bkh[cur][1]);
                MMA16816H(sc[2 * jj + 1], qfh[kc], bkh[cur][2], bkh[cur][3]);
            }
        }

        int k0 = kt * 64;
#pragma unroll
        for (int j = 0; j < 8; j++)
#pragma unroll
            for (int e = 0; e < 4; e++) sc[j][e] *= SCALE2;
        if (kt == qt) {                      // diagonal tile
            int rg0 = q0 + 16 * w + rq, rg1 = rg0 + 8;
#pragma unroll
            for (int j = 0; j < 8; j++) {
                int cg = k0 + 8 * j + 2 * cq;
                if (cg     > rg0) sc[j][0] = -1e30f;
                if (cg + 1 > rg0) sc[j][1] = -1e30f;
                if (cg     > rg1) sc[j][2] = -1e30f;
                if (cg + 1 > rg1) sc[j][3] = -1e30f;
            }
        }

        float t0 = -1e30f, t1 = -1e30f;
#pragma unroll
        for (int j = 0; j < 8; j++) {
            t0 = fmaxf(t0, fmaxf(sc[j][0], sc[j][1]));
            t1 = fmaxf(t1, fmaxf(sc[j][2], sc[j][3]));
        }
        t0 = fmaxf(t0, __shfl_xor_sync(0xffffffffu, t0, 1));
        t0 = fmaxf(t0, __shfl_xor_sync(0xffffffffu, t0, 2));
        t1 = fmaxf(t1, __shfl_xor_sync(0xffffffffu, t1, 1));
        t1 = fmaxf(t1, __shfl_xor_sync(0xffffffffu, t1, 2));
        float mn0 = fmaxf(m0, t0), mn1 = fmaxf(m1, t1);
        float al0 = ex2f(m0 - mn0), al1 = ex2f(m1 - mn1);
        m0 = mn0; m1 = mn1;
        l0 *= al0; l1 *= al1;
#pragma unroll
        for (int n = 0; n < 16; n++) {
            out[n][0] *= al0; out[n][1] *= al0;
            out[n][2] *= al1; out[n][3] *= al1;
        }

        // ---- exp + PV over 4 P-chunks (double-buffered V frags) ----
#pragma unroll
        for (int kc = 0; kc < 4; kc++) {
            int j0 = 2 * kc, j1 = 2 * kc + 1;
            float p00 = ex2f(sc[j0][0] - m0), p01 = ex2f(sc[j0][1] - m0);
            float p02 = ex2f(sc[j0][2] - m1), p03 = ex2f(sc[j0][3] - m1);
            float p10 = ex2f(sc[j1][0] - m0), p11 = ex2f(sc[j1][1] - m0);
            float p12 = ex2f(sc[j1][2] - m1), p13 = ex2f(sc[j1][3] - m1);
            l0 += p00 + p01 + p10 + p11;
            l1 += p02 + p03 + p12 + p13;

            uint32_t ah[4];
            ah[0] = packh(p00, p01);
            ah[1] = packh(p02, p03);
            ah[2] = packh(p10, p11);
            ah[3] = packh(p12, p13);

            uint32_t bvh[2][4];
            uint32_t o0 = voff + (uint32_t)kc * (16 * AROWB);
            LDSM4T(bvh[0], sS + o0);
#pragma unroll
            for (int jp = 0; jp < 8; jp++) {
                int cur = jp & 1;
                if (jp < 7)
                    LDSM4T(bvh[cur ^ 1], sS + o0 + (jp + 1) * 32);
                MMA16816H(out[2 * jp],     ah, bvh[cur][0], bvh[cur][1]);
                MMA16816H(out[2 * jp + 1], ah, bvh[cur][2], bvh[cur][3]);
            }
        }
    }

    l0 += __shfl_xor_sync(0xffffffffu, l0, 1);
    l0 += __shfl_xor_sync(0xffffffffu, l0, 2);
    l1 += __shfl_xor_sync(0xffffffffu, l1, 1);
    l1 += __shfl_xor_sync(0xffffffffu, l1, 2);
    float il0 = 1.f / l0, il1 = 1.f / l1;

    // Epilogue: write fp16 ctx plane (out-proj A operand)
    int b = bh >> 4, hh = bh & 15;
    int grow0 = b * SEQ + q0 + 16 * w + rq;
    __half* cb0 = g_cxh + (size_t)grow0 * KA + hh * HD + 2 * cq;
    __half* cb1 = cb0 + (size_t)8 * KA;
#pragma unroll
    for (int nt = 0; nt < 16; nt++) {
        *(uint32_t*)(cb0 + nt * 8) = packh(out[nt][0] * il0, out[nt][1] * il0);
        *(uint32_t*)(cb1 + nt * 8) = packh(out[nt][2] * il1, out[nt][3] * il1);
    }
}

// ---------------------------------------------------------------------------
// Launch graph (4 launches)
// ---------------------------------------------------------------------------
extern "C" void kernel_launch(void* const* d_in, const int* in_sizes, int n_in,
                              void* d_out, int out_size) {
    const float* x    = (const float*)d_in[0];
    // d_in[1] = attn_mask (pure causal) — reproduced analytically, not read
    const float* Wqkv = (const float*)d_in[2];
    const float* Wout = (const float*)d_in[3];
    float* out = (float*)d_out;

    __half *xh = 0, *wqp = 0, *wop = 0, *cxh = 0;
    cudaGetSymbolAddress((void**)&xh,  g_xh);
    cudaGetSymbolAddress((void**)&wqp, g_wqp);
    cudaGetSymbolAddress((void**)&wop, g_wop);
    cudaGetSymbolAddress((void**)&cxh, g_cxh);

    cudaFuncSetAttribute(tc_gemm_kernel,
                         cudaFuncAttributeMaxDynamicSharedMemorySize, GEMM_SMEM);
    cudaFuncSetAttribute(tc_gemm_qkv_kernel,
                         cudaFuncAttributeMaxDynamicSharedMemorySize, GEMM_SMEM);
    cudaFuncSetAttribute(attn_mma_kernel,
                         cudaFuncAttributeMaxDynamicSharedMemorySize, ATTN_SMEM);

    // idx 0: merged packs + RoPE table
    prep_kernel<<<(NPREP + 255) / 256, 256>>>(x, Wqkv, Wout);
    // idx 1: QKV GEMM with fused RoPE + fp16 pack epilogue
    tc_gemm_qkv_kernel<<<dim3(QKVN / 128, MROWS / 128), 128, GEMM_SMEM>>>(
        xh, wqp);
    // idx 2: attention (fp16, 64-row q-tiles, 2 CTAs/SM, LPT grid)
    attn_mma_kernel<<<(SEQ / 64) * BATCH * NH, 128, ATTN_SMEM>>>();
    // idx 3: output GEMM
    tc_gemm_kernel<<<dim3(HID / 128, MROWS / 128), 128, GEMM_SMEM>>>(
        cxh, wop, out, HID);
}

// round 17
// speedup vs baseline: 1.0125x; 1.0022x over previous
#include <cuda_runtime.h>
#include <cuda_bf16.h>
#include <cuda_fp16.h>
#include <math.h>
#include <stdint.h>

// Problem constants
#define SEQ   2048
#define HID   2048
#define NH    16
#define HD    128
#define BATCH 2
#define MROWS (BATCH * SEQ)     // 4096
#define QKVN  (3 * HID)         // 6144
#define KA    2048              // fp16 row length (single plane)

// softmax scale folded into q at pack time: 1/sqrt(128) * log2(e)
#define QSCALE 0.12754214004907056f

// ---------------------------------------------------------------------------
// Scratch (device globals — no runtime allocation allowed)
// ---------------------------------------------------------------------------
__device__ __align__(16) float g_cos[SEQ * 64];
__device__ __align__(16) float g_sin[SEQ * 64];
__device__ __align__(16) __half g_xh [(size_t)MROWS * KA];     // x, fp16
__device__ __align__(16) __half g_wqp[(size_t)QKVN  * KA];     // Wqkv fp16
__device__ __align__(16) __half g_wop[(size_t)HID   * KA];     // Wout fp16
__device__ __align__(16) __half g_cxh[(size_t)MROWS * KA];     // ctx, fp16
// attention operands (fp16, single plane each, per-(b,h) planar)
__device__ __align__(16) __half g_qp[(size_t)BATCH * NH * SEQ * HD];
__device__ __align__(16) __half g_kp[(size_t)BATCH * NH * SEQ * HD];
__device__ __align__(16) __half g_vp[(size_t)BATCH * NH * SEQ * HD];

// ---------------------------------------------------------------------------
// PTX helpers (arch-agnostic: cp.async / ldmatrix / mma.sync only)
// ---------------------------------------------------------------------------
__device__ __forceinline__ uint32_t s2u(const void* p) {
    uint32_t a;
    asm("{ .reg .u64 t; cvta.to.shared.u64 t, %1; cvt.u32.u64 %0, t; }"
        : "=r"(a) : "l"(p));
    return a;
}

#define CP_ASYNC16(saddr, gptr) \
    asm volatile("cp.async.cg.shared.global [%0], [%1], 16;" \
                 :: "r"(saddr), "l"(gptr))
#define CP_COMMIT()  asm volatile("cp.async.commit_group;" ::: "memory")
#define CP_WAIT1()   asm volatile("cp.async.wait_group 1;" ::: "memory")
#define CP_WAIT2()   asm volatile("cp.async.wait_group 2;" ::: "memory")

#define LDSM4(r, addr)                                                        \
    asm volatile("ldmatrix.sync.aligned.m8n8.x4.shared.b16 {%0,%1,%2,%3}, [%4];" \
        : "=r"((r)[0]), "=r"((r)[1]), "=r"((r)[2]), "=r"((r)[3]) : "r"(addr))
#define LDSM4T(r, addr)                                                       \
    asm volatile("ldmatrix.sync.aligned.m8n8.x4.trans.shared.b16 {%0,%1,%2,%3}, [%4];" \
        : "=r"((r)[0]), "=r"((r)[1]), "=r"((r)[2]), "=r"((r)[3]) : "r"(addr))

#define MMA16816H(d, a, b0, b1)                                               \
    asm volatile("mma.sync.aligned.m16n8k16.row.col.f32.f16.f16.f32 "         \
        "{%0,%1,%2,%3},{%4,%5,%6,%7},{%8,%9},{%0,%1,%2,%3};"                  \
        : "+f"((d)[0]), "+f"((d)[1]), "+f"((d)[2]), "+f"((d)[3])              \
        : "r"((a)[0]), "r"((a)[1]), "r"((a)[2]), "r"((a)[3]),                 \
          "r"(b0), "r"(b1))

__device__ __forceinline__ float ex2f(float x) {
    float y;
    asm("ex2.approx.ftz.f32 %0, %1;" : "=f"(y) : "f"(x));
    return y;
}
__device__ __forceinline__ uint32_t h2u(__half2 h) {
    return *(uint32_t*)&h;
}
__device__ __forceinline__ uint32_t packh(float lo, float hi) {
    __half2 h = __float22half2_rn(make_float2(lo, hi));
    return h2u(h);
}

// ---------------------------------------------------------------------------
// Merged prep: fp32 -> fp16 packs (x, Wqkv, Wout) + RoPE table, one launch.
// ---------------------------------------------------------------------------
#define NCX (MROWS * HID / 8)
#define NCQ (QKVN * HID / 8)
#define NCO (HID * HID / 8)
#define NC_ALL (NCX + NCQ + NCO)
#define NROPE (SEQ * 64)
#define NPREP (NC_ALL + NROPE)

__global__ void prep_kernel(const float* __restrict__ X,
                            const float* __restrict__ Wq,
                            const float* __restrict__ Wo) {
    int i = blockIdx.x * 256 + threadIdx.x;
    if (i >= NPREP) return;
    if (i >= NC_ALL) {
        int idx = i - NC_ALL;
        int s = idx >> 6;
        int j = idx & 63;
        double inv = exp(-((double)j / 64.0) * log(10000.0));
        float  invf = (float)inv;
        float  ang  = (float)s * invf;
        g_cos[idx] = (float)cos((double)ang);
        g_sin[idx] = (float)sin((double)ang);
        return;
    }
    const float* src;
    __half* dst;
    int off;
    if (i < NCX)            { src = X;  dst = g_xh;  off = i; }
    else if (i < NCX + NCQ) { src = Wq; dst = g_wqp; off = i - NCX; }
    else                    { src = Wo; dst = g_wop; off = i - NCX - NCQ; }
    size_t e = (size_t)off * 8;
    float4 a = *(const float4*)(src + e);
    float4 b = *(const float4*)(src + e + 4);
    *(uint4*)(dst + e) = make_uint4(
        packh(a.x, a.y), packh(a.z, a.w), packh(b.x, b.y), packh(b.z, b.w));
}

// ---------------------------------------------------------------------------
// Shared GEMM config
// ---------------------------------------------------------------------------
#define AST         72
#define STG_MAT     (128 * AST * 2)
#define STG_BYTES   (2 * STG_MAT)
#define GEMM_STAGES 3
#define GEMM_SMEM   (GEMM_STAGES * STG_BYTES)   // 110592
#define GNITER      32

__device__ __forceinline__ void g_load_stage(
    uint32_t sA, const __half* Ab, const __half* Bb, int tid)
{
#pragma unroll
    for (int t = 0; t < 8; t++) {
        int c = tid + t * 128;
        int r = c >> 3, co = (c & 7) << 3;
        CP_ASYNC16(sA + (r * AST + co) * 2, Ab + (size_t)r * KA + co);
        CP_ASYNC16(sA + STG_MAT + (r * AST + co) * 2, Bb + (size_t)r * KA + co);
    }
}

__device__ __forceinline__ void gemm_mainloop(
    uint32_t smb, const __half* A, const __half* B,
    int m0, int n0, int tid, int lane, int wm, int wn,
    float acc[4][8][4])
{
    uint32_t a_off[4][4], b_off[4][4];
#pragma unroll
    for (int ks = 0; ks < 4; ks++) {
#pragma unroll
        for (int mt = 0; mt < 4; mt++)
            a_off[ks][mt] = ((wm + mt * 16 + (lane & 15)) * AST +
                             ks * 16 + (lane >> 4) * 8) * 2;
#pragma unroll
        for (int np = 0; np < 4; np++)
            b_off[ks][np] = STG_MAT +
                ((wn + np * 16 + ((lane >> 4) & 1) * 8 + (lane & 7)) * AST +
                 ks * 16 + ((lane >> 3) & 1) * 8) * 2;
    }

#pragma unroll
    for (int p = 0; p < GEMM_STAGES - 1; p++) {
        g_load_stage(smb + p * STG_BYTES,
                     A + (size_t)m0 * KA + (p << 6),
                     B + (size_t)n0 * KA + (p << 6), tid);
        CP_COMMIT();
    }
    CP_WAIT1();
    __syncthreads();

    uint32_t af[2][4][4], bf[2][4];
#pragma unroll
    for (int mt = 0; mt < 4; mt++) LDSM4(af[0][mt], smb + a_off[0][mt]);
    LDSM4(bf[0], smb + b_off[0][0]);

    for (int it = 0; it < GNITER; ++it) {
        uint32_t sbase = smb + (it % GEMM_STAGES) * STG_BYTES;

        int nx = it + GEMM_STAGES - 1;
        if (nx < GNITER) {
            g_load_stage(smb + (nx % GEMM_STAGES) * STG_BYTES,
                         A + (size_t)m0 * KA + (nx << 6),
                         B + (size_t)n0 * KA + (nx << 6), tid);
        }
        CP_COMMIT();

#pragma unroll
        for (int ks = 0; ks < 4; ks++) {
            int cur = ks & 1, nxt = cur ^ 1;
            uint32_t bb[2][4];
#pragma unroll
            for (int e = 0; e < 4; e++) bb[0][e] = bf[cur][e];
#pragma unroll
            for (int np = 0; np < 4; np++) {
                if (np < 3) LDSM4(bb[(np + 1) & 1], sbase + b_off[ks][np + 1]);
#pragma unroll
                for (int mt = 0; mt < 4; mt++) {
                    MMA16816H(acc[mt][2 * np],     af[cur][mt], bb[np & 1][0], bb[np & 1][1]);
                    MMA16816H(acc[mt][2 * np + 1], af[cur][mt], bb[np & 1][2], bb[np & 1][3]);
                }
            }
            if (ks < 3) {
#pragma unroll
                for (int mt = 0; mt < 4; mt++)
                    LDSM4(af[nxt][mt], sbase + a_off[ks + 1][mt]);
                LDSM4(bf[nxt], sbase + b_off[ks + 1][0]);
            }
        }

        CP_WAIT1();
        __syncthreads();
        uint32_t nbase = smb + ((it + 1) % GEMM_STAGES) * STG_BYTES;
#pragma unroll
        for (int mt = 0; mt < 4; mt++) LDSM4(af[0][mt], nbase + a_off[0][mt]);
        LDSM4(bf[0], nbase + b_off[0][0]);
    }
}

// ---------------------------------------------------------------------------
// Out-projection GEMM: fp32 epilogue to C
// ---------------------------------------------------------------------------
__global__ void __launch_bounds__(128, 2) tc_gemm_kernel(
    const __half* __restrict__ A, const __half* __restrict__ B,
    float* __restrict__ C, int ldc)
{
    extern __shared__ char smg[];
    uint32_t smb = s2u(smg);
    int tid  = threadIdx.x;
    int lane = tid & 31, wid = tid >> 5;
    int wm = (wid & 1) * 64, wn = (wid >> 1) * 64;
    int m0 = blockIdx.y * 128, n0 = blockIdx.x * 128;

    float acc[4][8][4];
#pragma unroll
    for (int i = 0; i < 4; i++)
#pragma unroll
        for (int j = 0; j < 8; j++)
#pragma unroll
            for (int k = 0; k < 4; k++) acc[i][j][k] = 0.f;

    gemm_mainloop(smb, A, B, m0, n0, tid, lane, wm, wn, acc);

    float* Cb = C + (size_t)(m0 + wm) * ldc + n0 + wn;
    int rq = lane >> 2, cq = (lane & 3) * 2;
#pragma unroll
    for (int mt = 0; mt < 4; mt++)
#pragma unroll
        for (int nt = 0; nt < 8; nt++) {
            *(float2*)(Cb + (size_t)(mt * 16 + rq) * ldc + nt * 8 + cq) =
                make_float2(acc[mt][nt][0], acc[mt][nt][1]);
            *(float2*)(Cb + (size_t)(mt * 16 + rq + 8) * ldc + nt * 8 + cq) =
                make_float2(acc[mt][nt][2], acc[mt][nt][3]);
        }
}

// ---------------------------------------------------------------------------
// QKV GEMM with fused RoPE + fp16 pack epilogue.
// q region: RoPE + QSCALE (softmax scale folded in) via smem exchange.
// k region: RoPE via smem exchange.
// v region: register fast path — direct acc -> fp16 stores, no smem staging.
// ---------------------------------------------------------------------------
#define EP_STR 132

__global__ void __launch_bounds__(128, 2) tc_gemm_qkv_kernel(
    const __half* __restrict__ A, const __half* __restrict__ B)
{
    extern __shared__ char smg[];
    uint32_t smb = s2u(smg);
    int tid  = threadIdx.x;
    int lane = tid & 31, wid = tid >> 5;
    int wm = (wid & 1) * 64, wn = (wid >> 1) * 64;
    int m0 = blockIdx.y * 128, n0 = blockIdx.x * 128;

    float acc[4][8][4];
#pragma unroll
    for (int i = 0; i < 4; i++)
#pragma unroll
        for (int j = 0; j < 8; j++)
#pragma unroll
            for (int k = 0; k < 4; k++) acc[i][j][k] = 0.f;

    gemm_mainloop(smb, A, B, m0, n0, tid, lane, wm, wn, acc);

    int region = n0 >> 11;           // 0:q 1:k 2:v
    int head   = (n0 & 2047) >> 7;
    int rq = lane >> 2, cq2 = (lane & 3) * 2;

    if (region == 2) {
        // v: register fast path (no smem, no barriers)
#pragma unroll
        for (int mt = 0; mt < 4; mt++) {
            int gr0 = m0 + wm + mt * 16 + rq;
            int s0 = gr0 & (SEQ - 1), b0i = gr0 >> 11;
            size_t base0 = (((size_t)(b0i * NH + head)) * SEQ + s0) * HD;
            int gr1 = gr0 + 8;
            int s1 = gr1 & (SEQ - 1), b1i = gr1 >> 11;
            size_t base1 = (((size_t)(b1i * NH + head)) * SEQ + s1) * HD;
#pragma unroll
            for (int nt = 0; nt < 8; nt++) {
                int c = wn + nt * 8 + cq2;
                *(uint32_t*)(g_vp + base0 + c) =
                    packh(acc[mt][nt][0], acc[mt][nt][1]);
                *(uint32_t*)(g_vp + base1 + c) =
                    packh(acc[mt][nt][2], acc[mt][nt][3]);
            }
        }
        return;
    }

    // q/k: stage through smem for the cross-warp RoPE pairing
    __syncthreads();
    float* st = (float*)smg;
#pragma unroll
    for (int mt = 0; mt < 4; mt++)
#pragma unroll
        for (int nt = 0; nt < 8; nt++) {
            int c = wn + nt * 8 + cq2;
            *(float2*)&st[(wm + mt * 16 + rq) * EP_STR + c] =
                make_float2(acc[mt][nt][0], acc[mt][nt][1]);
            *(float2*)&st[(wm + mt * 16 + rq + 8) * EP_STR + c] =
                make_float2(acc[mt][nt][2], acc[mt][nt][3]);
        }
    __syncthreads();

    __half* dst = (region == 0) ? g_qp : g_kp;
    float scl   = (region == 0) ? QSCALE : 1.f;
    for (int t = tid; t < 2048; t += 128) {
        int r  = t >> 4;
        int jg = (t & 15) << 2;
        int gr = m0 + r;
        int s  = gr & (SEQ - 1);
        int bh = (gr >> 11) * NH + head;
        float4 S1 = *(float4*)&st[r * EP_STR + jg];
        float4 S2 = *(float4*)&st[r * EP_STR + jg + 64];
        float4 c4 = *(const float4*)&g_cos[(s << 6) + jg];
        float4 s4 = *(const float4*)&g_sin[(s << 6) + jg];
        float a0 = (S1.x * c4.x - S2.x * s4.x) * scl;
        float a1 = (S1.y * c4.y - S2.y * s4.y) * scl;
        float a2 = (S1.z * c4.z - S2.z * s4.z) * scl;
        float a3 = (S1.w * c4.w - S2.w * s4.w) * scl;
        float b0 = (S2.x * c4.x + S1.x * s4.x) * scl;
        float b1 = (S2.y * c4.y + S1.y * s4.y) * scl;
        float b2 = (S2.z * c4.z + S1.z * s4.z) * scl;
        float b3 = (S2.w * c4.w + S1.w * s4.w) * scl;
        size_t base = ((size_t)bh * SEQ + s) * HD;
        *(uint2*)(dst + base + jg) =
            make_uint2(packh(a0, a1), packh(a2, a3));
        *(uint2*)(dst + base + jg + 64) =
            make_uint2(packh(b0, b1), packh(b2, b3));
    }
}

// ---------------------------------------------------------------------------
// Tensor-core flash attention: fp16 1-pass, 128-thread CTAs (2 CTAs/SM),
// 64-row q-tiles, BK=64, 3-slot ring w/ Q borrowing slot 2, causal,
// online softmax (scale pre-folded into q), LPT grid, conditional rescale,
// fused fp16 ctx epilogue.
// ---------------------------------------------------------------------------
#define AKST     136
#define AROWB    (AKST * 2)                 // 272 B
#define KVPLANE  (64 * AROWB)               // 17408
#define SLOT_B   (2 * KVPLANE)              // 34816
#define ATTN_SMEM (3 * SLOT_B)              // 104448 -> 2 CTAs/SM

__device__ __forceinline__ void load_kv_stage(
    uint32_t dst, const __half* Kp, const __half* Vp, int k0, int tid)
{
#pragma unroll
    for (int t = 0; t < 16; t++) {
        int c = tid + t * 128;
        int plane = c >> 10;                // 0:K 1:V
        int r = (c >> 4) & 63;
        int co = c & 15;
        const __half* src = (plane == 0)
            ? Kp + ((size_t)k0 + r) * HD + co * 8
            : Vp + ((size_t)k0 + r) * HD + co * 8;
        CP_ASYNC16(dst + plane * KVPLANE + r * AROWB + co * 16, src);
    }
}

__global__ void __launch_bounds__(128, 2) attn_mma_kernel() {
    extern __shared__ char sma[];
    uint32_t smb = s2u(sma);
    int tid = threadIdx.x, lane = tid & 31, w = tid >> 5;
    int qt = 31 - ((int)blockIdx.x >> 5);   // LPT: heaviest first
    int bh = (int)blockIdx.x & 31;
    int q0 = qt * 64;
    int nkt = qt + 1;

    const __half* Qp = g_qp + (size_t)bh * SEQ * HD;
    const __half* Kp = g_kp + (size_t)bh * SEQ * HD;
    const __half* Vp = g_vp + (size_t)bh * SEQ * HD;

    uint32_t sQstage = smb + 2 * SLOT_B;
#pragma unroll
    for (int t = 0; t < 8; t++) {
        int c = tid + t * 128;
        int r = c >> 4, co = c & 15;
        CP_ASYNC16(sQstage + r * AROWB + co * 16,
                   Qp + ((size_t)q0 + r) * HD + co * 8);
    }
    CP_COMMIT();
    load_kv_stage(smb, Kp, Vp, 0, tid);
    CP_COMMIT();
    load_kv_stage(smb + SLOT_B, Kp, Vp, 64, tid);   // prefetch (valid mem)
    CP_COMMIT();

    int rq = lane >> 2, cq = lane & 3;
    uint32_t qoff = (uint32_t)(16 * w + (lane & 15)) * AROWB + ((lane >> 4) & 1) * 16;
    uint32_t koff = (uint32_t)(((lane >> 4) & 1) * 8 + (lane & 7)) * AROWB +
                    ((lane >> 3) & 1) * 16;
    uint32_t voff = KVPLANE +
                    (uint32_t)(((lane >> 3) & 1) * 8 + (lane & 7)) * AROWB +
                    ((lane >> 4) & 1) * 16;

    CP_WAIT2();
    __syncthreads();
    uint32_t qfh[8][4];
#pragma unroll
    for (int kc = 0; kc < 8; kc++)
        LDSM4(qfh[kc], sQstage + qoff + kc * 32);

    float out[16][4];
#pragma unroll
    for (int n = 0; n < 16; n++)
#pragma unroll
        for (int e = 0; e < 4; e++) out[n][e] = 0.f;
    float m0 = -1e30f, m1 = -1e30f, l0 = 0.f, l1 = 0.f;

    for (int kt = 0; kt < nkt; kt++) {
        CP_WAIT1();
        __syncthreads();
        if (kt + 2 < nkt)
            load_kv_stage(smb + ((kt + 2) % 3) * SLOT_B, Kp, Vp,
                          (kt + 2) * 64, tid);
        CP_COMMIT();

        uint32_t sS = smb + (kt % 3) * SLOT_B;

        // ---- scores: S[64x64] per warp m16 (scale pre-folded into q) ----
        float sc[8][4];
#pragma unroll
        for (int j = 0; j < 8; j++)
#pragma unroll
            for (int e = 0; e < 4; e++) sc[j][e] = 0.f;

        {
            uint32_t bkh[2][4];
            LDSM4(bkh[0], sS + koff);
#pragma unroll
            for (int t = 0; t < 32; t++) {
                int kc = t >> 2, jj = t & 3;
                int cur = t & 1;
                if (t < 31) {
                    int tn = t + 1;
                    uint32_t on = koff + (uint32_t)(tn & 3) * (16 * AROWB) +
                                  (tn >> 2) * 32;
                    LDSM4(bkh[cur ^ 1], sS + on);
                }
                MMA16816H(sc[2 * jj],     qfh[kc], bkh[cur][0], bkh[cur][1]);
                MMA16816H(sc[2 * jj + 1], qfh[kc], bkh[cur][2], bkh[cur][3]);
            }
        }

        int k0 = kt * 64;
        if (kt == qt) {                      // diagonal tile: causal mask
            int rg0 = q0 + 16 * w + rq, rg1 = rg0 + 8;
#pragma unroll
            for (int j = 0; j < 8; j++) {
                int cg = k0 + 8 * j + 2 * cq;
                if (cg     > rg0) sc[j][0] = -1e30f;
                if (cg + 1 > rg0) sc[j][1] = -1e30f;
                if (cg     > rg1) sc[j][2] = -1e30f;
                if (cg + 1 > rg1) sc[j][3] = -1e30f;
            }
        }

        float t0 = -1e30f, t1 = -1e30f;
#pragma unroll
        for (int j = 0; j < 8; j++) {
            t0 = fmaxf(t0, fmaxf(sc[j][0], sc[j][1]));
            t1 = fmaxf(t1, fmaxf(sc[j][2], sc[j][3]));
        }
        t0 = fmaxf(t0, __shfl_xor_sync(0xffffffffu, t0, 1));
        t0 = fmaxf(t0, __shfl_xor_sync(0xffffffffu, t0, 2));
        t1 = fmaxf(t1, __shfl_xor_sync(0xffffffffu, t1, 1));
        t1 = fmaxf(t1, __shfl_xor_sync(0xffffffffu, t1, 2));
        float mn0 = fmaxf(m0, t0), mn1 = fmaxf(m1, t1);
        float al0 = ex2f(m0 - mn0), al1 = ex2f(m1 - mn1);
        m0 = mn0; m1 = mn1;
        l0 *= al0; l1 *= al1;
        // skip the 64-FMA accumulator rescale when no row max changed
        if (!__all_sync(0xffffffffu, (al0 == 1.f) && (al1 == 1.f))) {
#pragma unroll
            for (int n = 0; n < 16; n++) {
                out[n][0] *= al0; out[n][1] *= al0;
                out[n][2] *= al1; out[n][3] *= al1;
            }
        }

        // ---- exp + PV over 4 P-chunks (double-buffered V frags) ----
#pragma unroll
        for (int kc = 0; kc < 4; kc++) {
            int j0 = 2 * kc, j1 = 2 * kc + 1;
            float p00 = ex2f(sc[j0][0] - m0), p01 = ex2f(sc[j0][1] - m0);
            float p02 = ex2f(sc[j0][2] - m1), p03 = ex2f(sc[j0][3] - m1);
            float p10 = ex2f(sc[j1][0] - m0), p11 = ex2f(sc[j1][1] - m0);
            float p12 = ex2f(sc[j1][2] - m1), p13 = ex2f(sc[j1][3] - m1);
            l0 += p00 + p01 + p10 + p11;
            l1 += p02 + p03 + p12 + p13;

            uint32_t ah[4];
            ah[0] = packh(p00, p01);
            ah[1] = packh(p02, p03);
            ah[2] = packh(p10, p11);
            ah[3] = packh(p12, p13);

            uint32_t bvh[2][4];
            uint32_t o0 = voff + (uint32_t)kc * (16 * AROWB);
            LDSM4T(bvh[0], sS + o0);
#pragma unroll
            for (int jp = 0; jp < 8; jp++) {
                int cur = jp & 1;
                if (jp < 7)
                    LDSM4T(bvh[cur ^ 1], sS + o0 + (jp + 1) * 32);
                MMA16816H(out[2 * jp],     ah, bvh[cur][0], bvh[cur][1]);
                MMA16816H(out[2 * jp + 1], ah, bvh[cur][2], bvh[cur][3]);
            }
        }
    }

    l0 += __shfl_xor_sync(0xffffffffu, l0, 1);
    l0 += __shfl_xor_sync(0xffffffffu, l0, 2);
    l1 += __shfl_xor_sync(0xffffffffu, l1, 1);
    l1 += __shfl_xor_sync(0xffffffffu, l1, 2);
    float il0 = 1.f / l0, il1 = 1.f / l1;

    int b = bh >> 4, hh = bh & 15;
    int grow0 = b * SEQ + q0 + 16 * w + rq;
    __half* cb0 = g_cxh + (size_t)grow0 * KA + hh * HD + 2 * cq;
    __half* cb1 = cb0 + (size_t)8 * KA;
#pragma unroll
    for (int nt = 0; nt < 16; nt++) {
        *(uint32_t*)(cb0 + nt * 8) = packh(out[nt][0] * il0, out[nt][1] * il0);
        *(uint32_t*)(cb1 + nt * 8) = packh(out[nt][2] * il1, out[nt][3] * il1);
    }
}

// ---------------------------------------------------------------------------
// Launch graph (4 launches)
// ---------------------------------------------------------------------------
extern "C" void kernel_launch(void* const* d_in, const int* in_sizes, int n_in,
                              void* d_out, int out_size) {
    const float* x    = (const float*)d_in[0];
    // d_in[1] = attn_mask (pure causal) — reproduced analytically, not read
    const float* Wqkv = (const float*)d_in[2];
    const float* Wout = (const float*)d_in[3];
    float* out = (float*)d_out;

    __half *xh = 0, *wqp = 0, *wop = 0, *cxh = 0;
    cudaGetSymbolAddress((void**)&xh,  g_xh);
    cudaGetSymbolAddress((void**)&wqp, g_wqp);
    cudaGetSymbolAddress((void**)&wop, g_wop);
    cudaGetSymbolAddress((void**)&cxh, g_cxh);

    cudaFuncSetAttribute(tc_gemm_kernel,
                         cudaFuncAttributeMaxDynamicSharedMemorySize, GEMM_SMEM);
    cudaFuncSetAttribute(tc_gemm_qkv_kernel,
                         cudaFuncAttributeMaxDynamicSharedMemorySize, GEMM_SMEM);
    cudaFuncSetAttribute(attn_mma_kernel,
                         cudaFuncAttributeMaxDynamicSharedMemorySize, ATTN_SMEM);

    // idx 0: merged packs + RoPE table
    prep_kernel<<<(NPREP + 255) / 256, 256>>>(x, Wqkv, Wout);
    // idx 1: QKV GEMM with fused RoPE/scale/pack epilogue
    tc_gemm_qkv_kernel<<<dim3(QKVN / 128, MROWS / 128), 128, GEMM_SMEM>>>(
        xh, wqp);
    // idx 2: attention (fp16, 64-row q-tiles, 2 CTAs/SM, LPT grid)
    attn_mma_kernel<<<(SEQ / 64) * BATCH * NH, 128, ATTN_SMEM>>>();
    // idx 3: output GEMM
    tc_gemm_kernel<<<dim3(HID / 128, MROWS / 128), 128, GEMM_SMEM>>>(
        cxh, wop, out, HID);
}